// round 12
// baseline (speedup 1.0000x reference)
#include <cuda_runtime.h>
#include <math.h>
#include <stdint.h>

// ---------------------------------------------------------------------------
// Problem constants
// ---------------------------------------------------------------------------
#define Bn    16
#define Cn    1024
#define Dn    512
#define Hn    8
#define HDn   64
#define En    8
#define Ktop  2
#define FFn   2048
#define Tn    (Bn*Cn)        /* 16384 tokens */
#define CAPn  5120
#define NSLOT (Tn*Ktop)      /* 32768 slots  */

// ---------------------------------------------------------------------------
// Scratch (~575 MB)
// ---------------------------------------------------------------------------
static constexpr size_t NPROJ    = (size_t)Tn * Dn;
static constexpr size_t OFF_Q    = 0;
static constexpr size_t OFF_K    = 1 * NPROJ;
static constexpr size_t OFF_V    = 2 * NPROJ;
static constexpr size_t OFF_ATTN = 3 * NPROJ;
static constexpr size_t OFF_PRJ  = OFF_Q;
static constexpr size_t OFF_SRC  = OFF_K;
static constexpr size_t OFF_DISP = OFF_V;
static constexpr size_t NDISP    = (size_t)En * CAPn * Dn;
static constexpr size_t OFF_H    = OFF_DISP + NDISP;
static constexpr size_t NH       = (size_t)En * CAPn * FFn;
static constexpr size_t OFF_Y    = OFF_H + NH;
static constexpr size_t OFF_TOPW = OFF_Y + NDISP;
static constexpr size_t NWPROJ   = (size_t)Dn * Dn;
static constexpr size_t OFF_WQKV = OFF_TOPW + NSLOT;        // 3 packed weights
static constexpr size_t OFF_BQKV = OFF_WQKV + 3 * NWPROJ;   // 3 packed biases
static constexpr size_t SCRATCH_FLOATS = OFF_BQKV + 3 * Dn;

__device__ float g_scratch[SCRATCH_FLOATS];
__device__ int   g_iscratch[2 * NSLOT + 8];

// ---------------------------------------------------------------------------
static __device__ __forceinline__ float gelu_fn(float x) {
    float x3 = x * x * x;
    float u  = 0.7978845608028654f * (x + 0.044715f * x3);
    return 0.5f * x * (1.0f + tanhf(u));
}

#define MMA_TF32(acc, a, b0, b1)                                              \
    asm volatile(                                                             \
        "mma.sync.aligned.m16n8k8.row.col.f32.tf32.tf32.f32 "                 \
        "{%0,%1,%2,%3}, {%4,%5,%6,%7}, {%8,%9}, {%0,%1,%2,%3};"               \
        : "+f"(acc[0]), "+f"(acc[1]), "+f"(acc[2]), "+f"(acc[3])              \
        : "r"(a[0]), "r"(a[1]), "r"(a[2]), "r"(a[3]), "r"(b0), "r"(b1))

static __device__ __forceinline__ void cp_async16(uint32_t saddr, const float* g) {
    asm volatile("cp.async.cg.shared.global [%0], [%1], 16;" :: "r"(saddr), "l"(g));
}

// ---------------------------------------------------------------------------
// tf32 tensor-core GEMM, 3-stage cp.async pipeline, z-batched.
//   C[z][M,N] = A[z][M,K] @ B[z][K,N] + bias[z]   (opt GELU)
// 128x128x32 block tile, 128 threads (4 warps 2x2), warp tile 64x64.
// RAW-BITS tf32: fp32 smem words are fed to the MMA unchanged (the HW
// truncates the low 13 mantissa bits) -> zero cvt instructions in the
// mainloop, no pre-round pass.  mcount[z] early-exit.
// ---------------------------------------------------------------------------
#define BM 128
#define BN 128
#define BKt 32
#define ASTRIDE 36
#define BSTRIDE 136
#define ASTAGE (BM * ASTRIDE)              // 4608 floats
#define BSTAGE (BKt * BSTRIDE)             // 4352 floats
#define GEMM_SMEM_BYTES ((3 * (ASTAGE + BSTAGE)) * 4)   // 107520

template <bool GELU>
__global__ __launch_bounds__(128) void gemm_tc_kernel(
    const float* __restrict__ A, int lda, size_t aZ,
    const float* __restrict__ Bm, int ldb, size_t bZ,
    const float* __restrict__ bias, int biasZ,
    float* __restrict__ C, int ldc, size_t cZ,
    int Kd, const int* __restrict__ mcount)
{
    const int z = blockIdx.z;
    if (mcount && (int)(blockIdx.y * BM) >= mcount[z]) return;

    extern __shared__ float dsm[];
    float* Asm = dsm;                       // [3][BM][ASTRIDE]
    float* Bsm = dsm + 3 * ASTAGE;          // [3][BKt][BSTRIDE]

    const int tid  = threadIdx.x;
    const int wid  = tid >> 5;
    const int lane = tid & 31;
    const int wm   = (wid & 1) * 64;
    const int wnn  = (wid >> 1) * 64;
    const int g    = lane >> 2;
    const int tg   = lane & 3;

    const int arow = tid >> 3;            // 0..15
    const int acol = (tid & 7) * 4;       // 0..28
    const int brow = tid >> 5;            // 0..3
    const int bcol = (tid & 31) * 4;      // 0..124

    const float* Ag = A + z * aZ + (size_t)(blockIdx.y * BM + arow) * lda + acol;
    const float* Bg = Bm + z * bZ + (size_t)brow * ldb + blockIdx.x * BN + bcol;

    const uint32_t asb = (uint32_t)__cvta_generic_to_shared(Asm) +
                         (arow * ASTRIDE + acol) * 4;
    const uint32_t bsb = (uint32_t)__cvta_generic_to_shared(Bsm) +
                         (brow * BSTRIDE + bcol) * 4;

    const int ntile = Kd / BKt;

#define GEMM_PREFETCH(stage, kt)                                              \
    do {                                                                      \
        const float* ga = Ag + (kt) * BKt;                                    \
        const float* gb = Bg + (size_t)(kt) * BKt * ldb;                      \
        uint32_t sa = asb + (stage) * (ASTAGE * 4);                           \
        uint32_t sb = bsb + (stage) * (BSTAGE * 4);                           \
        _Pragma("unroll")                                                     \
        for (int s = 0; s < 8; s++)                                           \
            cp_async16(sa + s * (16 * ASTRIDE * 4), ga + (size_t)s * 16 * lda);\
        _Pragma("unroll")                                                     \
        for (int s = 0; s < 8; s++)                                           \
            cp_async16(sb + s * (4 * BSTRIDE * 4), gb + (size_t)s * 4 * ldb); \
        asm volatile("cp.async.commit_group;");                               \
    } while (0)

    GEMM_PREFETCH(0, 0);
    if (ntile > 1) GEMM_PREFETCH(1, 1);
    else asm volatile("cp.async.commit_group;");

    float acc[4][8][4];
    #pragma unroll
    for (int i = 0; i < 4; i++)
        #pragma unroll
        for (int j = 0; j < 8; j++) {
            acc[i][j][0] = 0.f; acc[i][j][1] = 0.f;
            acc[i][j][2] = 0.f; acc[i][j][3] = 0.f;
        }

    for (int kt = 0; kt < ntile; kt++) {
        if (kt + 2 < ntile) {
            GEMM_PREFETCH((kt + 2) % 3, kt + 2);
            asm volatile("cp.async.wait_group 2;");
        } else if (kt + 1 < ntile) {
            asm volatile("cp.async.wait_group 1;");
        } else {
            asm volatile("cp.async.wait_group 0;");
        }
        __syncthreads();

        const uint32_t* Ab = (const uint32_t*)(Asm + (kt % 3) * ASTAGE);
        const uint32_t* Bb = (const uint32_t*)(Bsm + (kt % 3) * BSTAGE);

        #pragma unroll
        for (int kc = 0; kc < 4; kc++) {
            const int k0 = kc * 8;
            uint32_t afr[4][4];
            #pragma unroll
            for (int i = 0; i < 4; i++) {
                const uint32_t* ra = Ab + (wm + i * 16 + g) * ASTRIDE + k0;
                const uint32_t* rb = ra + 8 * ASTRIDE;
                afr[i][0] = ra[tg];
                afr[i][1] = rb[tg];
                afr[i][2] = ra[tg + 4];
                afr[i][3] = rb[tg + 4];
            }
            uint32_t bfr[8][2];
            #pragma unroll
            for (int j = 0; j < 8; j++) {
                int n = wnn + j * 8 + g;
                bfr[j][0] = Bb[(k0 + tg) * BSTRIDE + n];
                bfr[j][1] = Bb[(k0 + tg + 4) * BSTRIDE + n];
            }
            #pragma unroll
            for (int i = 0; i < 4; i++)
                #pragma unroll
                for (int j = 0; j < 8; j++)
                    MMA_TF32(acc[i][j], afr[i], bfr[j][0], bfr[j][1]);
        }
        __syncthreads();
    }
#undef GEMM_PREFETCH

    // epilogue
    const float* bz = bias + (size_t)z * biasZ;
    float* Cz = C + z * cZ;
    #pragma unroll
    for (int j = 0; j < 8; j++) {
        const int col = blockIdx.x * BN + wnn + j * 8 + 2 * tg;
        const float2 bb = *(const float2*)(bz + col);
        #pragma unroll
        for (int i = 0; i < 4; i++) {
            const size_t row0 = (size_t)blockIdx.y * BM + wm + i * 16 + g;
            float2 v0, v1;
            v0.x = acc[i][j][0] + bb.x;
            v0.y = acc[i][j][1] + bb.y;
            v1.x = acc[i][j][2] + bb.x;
            v1.y = acc[i][j][3] + bb.y;
            if (GELU) {
                v0.x = gelu_fn(v0.x); v0.y = gelu_fn(v0.y);
                v1.x = gelu_fn(v1.x); v1.y = gelu_fn(v1.y);
            }
            *(float2*)(Cz + row0 * ldc + col)       = v0;
            *(float2*)(Cz + (row0 + 8) * ldc + col) = v1;
        }
    }
}

// ---------------------------------------------------------------------------
// Flash attention, tf32 tensor cores. R7 scalar-STS staging (fastest
// measured variant), raw-bits tf32 (no cvt anywhere).
// ---------------------------------------------------------------------------
__global__ __launch_bounds__(128) void attn_mma_kernel(
    const float* __restrict__ Q, const float* __restrict__ Kb,
    const float* __restrict__ V, const int* __restrict__ mask,
    float* __restrict__ O)
{
    __shared__ uint32_t sK[64][68];
    __shared__ uint32_t sV[64][72];
    __shared__ uint32_t sP[4][16][36];
    __shared__ int      sM[64];

    const int tid  = threadIdx.x;
    const int w    = tid >> 5;
    const int lane = tid & 31;
    const int g    = lane >> 2;
    const int tg   = lane & 3;

    const int bh = blockIdx.y;
    const int b  = bh >> 3, h = bh & 7;
    const int q0 = blockIdx.x << 6;
    const size_t rowbase = (size_t)b * Cn;

    const float* QB = Q  + (rowbase + q0) * Dn + h * HDn;
    const float* KB = Kb + rowbase * Dn + h * HDn;
    const float* VB = V  + rowbase * Dn + h * HDn;
    const int*   MB = mask + b * Cn;

    #pragma unroll
    for (int i = 0; i < 8; i++) {
        int slot = tid + i * 128;
        int r = slot >> 4, c4 = (slot & 15) << 2;
        float4 qv = *(const float4*)(QB + (size_t)r * Dn + c4);
        sK[r][c4 + 0] = __float_as_uint(qv.x * 0.125f);
        sK[r][c4 + 1] = __float_as_uint(qv.y * 0.125f);
        sK[r][c4 + 2] = __float_as_uint(qv.z * 0.125f);
        sK[r][c4 + 3] = __float_as_uint(qv.w * 0.125f);
    }
    __syncthreads();

    const int row0 = w * 16 + g;
    uint32_t qa[8][4];
    #pragma unroll
    for (int ks = 0; ks < 8; ks++) {
        qa[ks][0] = sK[row0][8 * ks + tg];
        qa[ks][1] = sK[row0 + 8][8 * ks + tg];
        qa[ks][2] = sK[row0][8 * ks + tg + 4];
        qa[ks][3] = sK[row0 + 8][8 * ks + tg + 4];
    }
    __syncthreads();

    float o[8][4];
    #pragma unroll
    for (int jn = 0; jn < 8; jn++) {
        o[jn][0] = 0.f; o[jn][1] = 0.f; o[jn][2] = 0.f; o[jn][3] = 0.f;
    }
    float mrun0 = -3.0e38f, mrun1 = -3.0e38f;
    float lrun0 = 0.f, lrun1 = 0.f;

    for (int kt = 0; kt < Cn / 64; kt++) {
        const int k0 = kt * 64;
        #pragma unroll
        for (int i = 0; i < 8; i++) {
            int slot = tid + i * 128;
            int r = slot >> 4, c4 = (slot & 15) << 2;
            float4 kv = *(const float4*)(KB + (size_t)(k0 + r) * Dn + c4);
            float4 vv = *(const float4*)(VB + (size_t)(k0 + r) * Dn + c4);
            sK[r][c4 + 0] = __float_as_uint(kv.x);
            sK[r][c4 + 1] = __float_as_uint(kv.y);
            sK[r][c4 + 2] = __float_as_uint(kv.z);
            sK[r][c4 + 3] = __float_as_uint(kv.w);
            sV[r][c4 + 0] = __float_as_uint(vv.x);
            sV[r][c4 + 1] = __float_as_uint(vv.y);
            sV[r][c4 + 2] = __float_as_uint(vv.z);
            sV[r][c4 + 3] = __float_as_uint(vv.w);
        }
        if (tid < 64) sM[tid] = MB[k0 + tid];
        __syncthreads();

        #pragma unroll
        for (int kc = 0; kc < 2; kc++) {
            float sacc[4][4];
            #pragma unroll
            for (int j = 0; j < 4; j++) {
                sacc[j][0] = 0.f; sacc[j][1] = 0.f;
                sacc[j][2] = 0.f; sacc[j][3] = 0.f;
            }
            #pragma unroll
            for (int ks = 0; ks < 8; ks++) {
                #pragma unroll
                for (int j = 0; j < 4; j++) {
                    int n = kc * 32 + 8 * j + g;
                    uint32_t b0 = sK[n][8 * ks + tg];
                    uint32_t b1 = sK[n][8 * ks + tg + 4];
                    MMA_TF32(sacc[j], qa[ks], b0, b1);
                }
            }

            #pragma unroll
            for (int j = 0; j < 4; j++) {
                int c = kc * 32 + 8 * j + 2 * tg;
                if (sM[c] == 0)     { sacc[j][0] = -1e10f; sacc[j][2] = -1e10f; }
                if (sM[c + 1] == 0) { sacc[j][1] = -1e10f; sacc[j][3] = -1e10f; }
            }

            float mx0 = -3.0e38f, mx1 = -3.0e38f;
            #pragma unroll
            for (int j = 0; j < 4; j++) {
                mx0 = fmaxf(mx0, fmaxf(sacc[j][0], sacc[j][1]));
                mx1 = fmaxf(mx1, fmaxf(sacc[j][2], sacc[j][3]));
            }
            mx0 = fmaxf(mx0, __shfl_xor_sync(0xffffffffu, mx0, 1));
            mx0 = fmaxf(mx0, __shfl_xor_sync(0xffffffffu, mx0, 2));
            mx1 = fmaxf(mx1, __shfl_xor_sync(0xffffffffu, mx1, 1));
            mx1 = fmaxf(mx1, __shfl_xor_sync(0xffffffffu, mx1, 2));

            float mnew0 = fmaxf(mrun0, mx0);
            float mnew1 = fmaxf(mrun1, mx1);
            float corr0 = __expf(mrun0 - mnew0);
            float corr1 = __expf(mrun1 - mnew1);
            mrun0 = mnew0; mrun1 = mnew1;

            float p[4][4];
            float ls0 = 0.f, ls1 = 0.f;
            #pragma unroll
            for (int j = 0; j < 4; j++) {
                p[j][0] = __expf(sacc[j][0] - mnew0);
                p[j][1] = __expf(sacc[j][1] - mnew0);
                p[j][2] = __expf(sacc[j][2] - mnew1);
                p[j][3] = __expf(sacc[j][3] - mnew1);
                ls0 += p[j][0] + p[j][1];
                ls1 += p[j][2] + p[j][3];
            }
            ls0 += __shfl_xor_sync(0xffffffffu, ls0, 1);
            ls0 += __shfl_xor_sync(0xffffffffu, ls0, 2);
            ls1 += __shfl_xor_sync(0xffffffffu, ls1, 1);
            ls1 += __shfl_xor_sync(0xffffffffu, ls1, 2);
            lrun0 = lrun0 * corr0 + ls0;
            lrun1 = lrun1 * corr1 + ls1;

            #pragma unroll
            for (int jn = 0; jn < 8; jn++) {
                o[jn][0] *= corr0; o[jn][1] *= corr0;
                o[jn][2] *= corr1; o[jn][3] *= corr1;
            }

            #pragma unroll
            for (int j = 0; j < 4; j++) {
                int c = 8 * j + 2 * tg;
                sP[w][g][c]         = __float_as_uint(p[j][0]);
                sP[w][g][c + 1]     = __float_as_uint(p[j][1]);
                sP[w][g + 8][c]     = __float_as_uint(p[j][2]);
                sP[w][g + 8][c + 1] = __float_as_uint(p[j][3]);
            }
            __syncwarp();

            uint32_t pa[4][4];
            #pragma unroll
            for (int ks = 0; ks < 4; ks++) {
                pa[ks][0] = sP[w][g][8 * ks + tg];
                pa[ks][1] = sP[w][g + 8][8 * ks + tg];
                pa[ks][2] = sP[w][g][8 * ks + tg + 4];
                pa[ks][3] = sP[w][g + 8][8 * ks + tg + 4];
            }
            __syncwarp();

            #pragma unroll
            for (int ks = 0; ks < 4; ks++) {
                int kr = kc * 32 + 8 * ks;
                #pragma unroll
                for (int jn = 0; jn < 8; jn++) {
                    uint32_t b0 = sV[kr + tg][8 * jn + g];
                    uint32_t b1 = sV[kr + tg + 4][8 * jn + g];
                    MMA_TF32(o[jn], pa[ks], b0, b1);
                }
            }
        }
        __syncthreads();
    }

    const float inv0 = 1.0f / lrun0;
    const float inv1 = 1.0f / lrun1;
    const size_t grow = rowbase + q0 + row0;
    #pragma unroll
    for (int jn = 0; jn < 8; jn++) {
        int col = h * HDn + 8 * jn + 2 * tg;
        float2 v0, v1;
        v0.x = o[jn][0] * inv0; v0.y = o[jn][1] * inv0;
        v1.x = o[jn][2] * inv1; v1.y = o[jn][3] * inv1;
        *(float2*)(O + grow * Dn + col)       = v0;
        *(float2*)(O + (grow + 8) * Dn + col) = v1;
    }
}

// ---------------------------------------------------------------------------
// Residual add + LayerNorm (R7 version).
// ---------------------------------------------------------------------------
__global__ __launch_bounds__(256) void add_ln_kernel(
    const float* __restrict__ A, const float* __restrict__ R,
    const float* __restrict__ gam, const float* __restrict__ bet,
    float* __restrict__ out)
{
    int w    = (blockIdx.x * 256 + threadIdx.x) >> 5;
    int lane = threadIdx.x & 31;
    const float4* a4 = (const float4*)(A + (size_t)w * Dn);
    const float4* r4 = (const float4*)(R + (size_t)w * Dn);
    float4 v[4];
    float s = 0.0f, s2 = 0.0f;
    #pragma unroll
    for (int i = 0; i < 4; i++) {
        float4 xa = a4[lane + i * 32], xr = r4[lane + i * 32];
        v[i].x = xa.x + xr.x; v[i].y = xa.y + xr.y;
        v[i].z = xa.z + xr.z; v[i].w = xa.w + xr.w;
        s  += v[i].x + v[i].y + v[i].z + v[i].w;
        s2 += v[i].x * v[i].x + v[i].y * v[i].y + v[i].z * v[i].z + v[i].w * v[i].w;
    }
    #pragma unroll
    for (int off = 16; off; off >>= 1) {
        s  += __shfl_xor_sync(0xffffffffu, s,  off);
        s2 += __shfl_xor_sync(0xffffffffu, s2, off);
    }
    float mean = s * (1.0f / Dn);
    float var  = s2 * (1.0f / Dn) - mean * mean;
    float inv  = rsqrtf(var + 1e-5f);
    const float4* g4 = (const float4*)gam;
    const float4* b4 = (const float4*)bet;
    float4* o4 = (float4*)(out + (size_t)w * Dn);
    #pragma unroll
    for (int i = 0; i < 4; i++) {
        float4 g = g4[lane + i * 32], be = b4[lane + i * 32];
        float4 r;
        r.x = (v[i].x - mean) * inv * g.x + be.x;
        r.y = (v[i].y - mean) * inv * g.y + be.y;
        r.z = (v[i].z - mean) * inv * g.z + be.z;
        r.w = (v[i].w - mean) * inv * g.w + be.w;
        o4[lane + i * 32] = r;
    }
}

// ---------------------------------------------------------------------------
// Router (R7 version, separate kernel).
// ---------------------------------------------------------------------------
__global__ __launch_bounds__(256) void router_kernel(
    const float* __restrict__ src, const float* __restrict__ rw,
    int* __restrict__ topi, float* __restrict__ topw)
{
    int w    = (blockIdx.x * 256 + threadIdx.x) >> 5;
    int lane = threadIdx.x & 31;
    const float* xr = src + (size_t)w * Dn;
    float acc[8] = {0, 0, 0, 0, 0, 0, 0, 0};
    for (int d = lane; d < Dn; d += 32) {
        float xv = xr[d];
        const float4* r4 = (const float4*)(rw + d * 8);
        float4 r0 = r4[0], r1 = r4[1];
        acc[0] += xv * r0.x; acc[1] += xv * r0.y; acc[2] += xv * r0.z; acc[3] += xv * r0.w;
        acc[4] += xv * r1.x; acc[5] += xv * r1.y; acc[6] += xv * r1.z; acc[7] += xv * r1.w;
    }
    #pragma unroll
    for (int e = 0; e < 8; e++)
        #pragma unroll
        for (int off = 16; off; off >>= 1)
            acc[e] += __shfl_xor_sync(0xffffffffu, acc[e], off);

    if (lane == 0) {
        float mx = acc[0];
        #pragma unroll
        for (int e = 1; e < 8; e++) mx = fmaxf(mx, acc[e]);
        float pe[8], sum = 0.0f;
        #pragma unroll
        for (int e = 0; e < 8; e++) { pe[e] = __expf(acc[e] - mx); sum += pe[e]; }
        float isum = 1.0f / sum;
        #pragma unroll
        for (int e = 0; e < 8; e++) pe[e] *= isum;
        int i1 = 0; float v1 = pe[0];
        #pragma unroll
        for (int e = 1; e < 8; e++) if (pe[e] > v1) { v1 = pe[e]; i1 = e; }
        int i2 = -1; float v2 = -1.0f;
        #pragma unroll
        for (int e = 0; e < 8; e++) if (e != i1 && pe[e] > v2) { v2 = pe[e]; i2 = e; }
        float wn = 1.0f / (v1 + v2);
        topi[2 * w]     = i1;  topi[2 * w + 1] = i2;
        topw[2 * w]     = v1 * wn;  topw[2 * w + 1] = v2 * wn;
    }
}

// ---------------------------------------------------------------------------
// Deterministic capacity scan (unchanged).
// ---------------------------------------------------------------------------
__global__ __launch_bounds__(1024) void scan_kernel(
    const int* __restrict__ topi, int* __restrict__ slotpos,
    int* __restrict__ ecnt)
{
    __shared__ int wtot[32][8];
    __shared__ int wbase[32][8];
    int tid = threadIdx.x, lane = tid & 31, wid = tid >> 5;
    int base = tid * 32;

    int eid[32];
    #pragma unroll
    for (int i = 0; i < 32; i++) eid[i] = topi[base + i];

    int c[8];
    #pragma unroll
    for (int e = 0; e < 8; e++) {
        int ce = 0;
        #pragma unroll
        for (int i = 0; i < 32; i++) ce += (eid[i] == e);
        c[e] = ce;
    }

    int inc[8], excl[8];
    #pragma unroll
    for (int e = 0; e < 8; e++) {
        int v = c[e];
        for (int off = 1; off < 32; off <<= 1) {
            int n = __shfl_up_sync(0xffffffffu, v, off);
            if (lane >= off) v += n;
        }
        inc[e] = v; excl[e] = v - c[e];
    }
    if (lane == 31) {
        #pragma unroll
        for (int e = 0; e < 8; e++) wtot[wid][e] = inc[e];
    }
    __syncthreads();
    if (wid == 0) {
        #pragma unroll
        for (int e = 0; e < 8; e++) {
            int t = wtot[lane][e];
            int v = t;
            for (int off = 1; off < 32; off <<= 1) {
                int n = __shfl_up_sync(0xffffffffu, v, off);
                if (lane >= off) v += n;
            }
            wbase[lane][e] = v - t;
            if (lane == 31) ecnt[e] = min(v, CAPn);
        }
    }
    __syncthreads();

    int run[8];
    #pragma unroll
    for (int e = 0; e < 8; e++) run[e] = wbase[wid][e] + excl[e];

    #pragma unroll
    for (int i = 0; i < 32; i++) {
        int e = eid[i];
        int p = 0;
        #pragma unroll
        for (int ee = 0; ee < 8; ee++)
            if (e == ee) { p = run[ee]; run[ee] = p + 1; }
        slotpos[base + i] = (p < CAPn) ? p : -1;
    }
}

// ---------------------------------------------------------------------------
// Scatter (unchanged).
// ---------------------------------------------------------------------------
__global__ __launch_bounds__(64) void scatter_kernel(
    const float* __restrict__ src, const int* __restrict__ topi,
    const int* __restrict__ slotpos, float* __restrict__ disp)
{
    int s = blockIdx.x;
    int p = slotpos[s];
    if (p < 0) return;
    int e   = topi[s];
    int tok = s >> 1;
    const float4* in4  = (const float4*)(src + (size_t)tok * Dn);
    float4*       out4 = (float4*)(disp + ((size_t)e * CAPn + p) * Dn);
    int t = threadIdx.x;
    out4[t]      = in4[t];
    out4[t + 64] = in4[t + 64];
}

// ---------------------------------------------------------------------------
// Combine + LN2 (unchanged).
// ---------------------------------------------------------------------------
__global__ __launch_bounds__(256) void combine_ln_kernel(
    const float* __restrict__ src, const float* __restrict__ y,
    const int* __restrict__ topi, const float* __restrict__ topw,
    const int* __restrict__ slotpos,
    const float* __restrict__ gam, const float* __restrict__ bet,
    float* __restrict__ out)
{
    int w    = (blockIdx.x * 256 + threadIdx.x) >> 5;
    int lane = threadIdx.x & 31;
    const float4* s4 = (const float4*)(src + (size_t)w * Dn);
    float4 v[4];
    #pragma unroll
    for (int i = 0; i < 4; i++) v[i] = s4[lane + i * 32];

    #pragma unroll
    for (int kk = 0; kk < 2; kk++) {
        int slot = 2 * w + kk;
        int p = slotpos[slot];
        if (p >= 0) {
            int e = topi[slot];
            float ww = topw[slot];
            const float4* y4 = (const float4*)(y + ((size_t)e * CAPn + p) * Dn);
            #pragma unroll
            for (int i = 0; i < 4; i++) {
                float4 yy = y4[lane + i * 32];
                v[i].x += ww * yy.x; v[i].y += ww * yy.y;
                v[i].z += ww * yy.z; v[i].w += ww * yy.w;
            }
        }
    }

    float s = 0.0f, s2 = 0.0f;
    #pragma unroll
    for (int i = 0; i < 4; i++) {
        s  += v[i].x + v[i].y + v[i].z + v[i].w;
        s2 += v[i].x * v[i].x + v[i].y * v[i].y + v[i].z * v[i].z + v[i].w * v[i].w;
    }
    #pragma unroll
    for (int off = 16; off; off >>= 1) {
        s  += __shfl_xor_sync(0xffffffffu, s,  off);
        s2 += __shfl_xor_sync(0xffffffffu, s2, off);
    }
    float mean = s * (1.0f / Dn);
    float var  = s2 * (1.0f / Dn) - mean * mean;
    float inv  = rsqrtf(var + 1e-5f);
    const float4* g4 = (const float4*)gam;
    const float4* b4 = (const float4*)bet;
    float4* o4 = (float4*)(out + (size_t)w * Dn);
    #pragma unroll
    for (int i = 0; i < 4; i++) {
        float4 g = g4[lane + i * 32], be = b4[lane + i * 32];
        float4 r;
        r.x = (v[i].x - mean) * inv * g.x + be.x;
        r.y = (v[i].y - mean) * inv * g.y + be.y;
        r.z = (v[i].z - mean) * inv * g.z + be.z;
        r.w = (v[i].w - mean) * inv * g.w + be.w;
        o4[lane + i * 32] = r;
    }
}

// ---------------------------------------------------------------------------
// Launch sequence
// ---------------------------------------------------------------------------
extern "C" void kernel_launch(void* const* d_in, const int* in_sizes, int n_in,
                              void* d_out, int out_size)
{
    const float* x    = (const float*)d_in[0];
    const int*   msk  = (const int*)  d_in[1];
    const float* wq   = (const float*)d_in[2];
    const float* bq   = (const float*)d_in[3];
    const float* wk   = (const float*)d_in[4];
    const float* bk   = (const float*)d_in[5];
    const float* wv   = (const float*)d_in[6];
    const float* bv   = (const float*)d_in[7];
    const float* wo   = (const float*)d_in[8];
    const float* bo   = (const float*)d_in[9];
    const float* ln1g = (const float*)d_in[10];
    const float* ln1b = (const float*)d_in[11];
    const float* ln2g = (const float*)d_in[12];
    const float* ln2b = (const float*)d_in[13];
    const float* rw   = (const float*)d_in[14];
    const float* w1   = (const float*)d_in[15];
    const float* b1   = (const float*)d_in[16];
    const float* w2   = (const float*)d_in[17];
    const float* b2   = (const float*)d_in[18];
    float* out = (float*)d_out;

    float* S = nullptr;
    int*   I = nullptr;
    cudaGetSymbolAddress((void**)&S, g_scratch);
    cudaGetSymbolAddress((void**)&I, g_iscratch);

    float* Qb   = S + OFF_Q;
    float* Kbuf = S + OFF_K;
    float* Vb   = S + OFF_V;
    float* ATT  = S + OFF_ATTN;
    float* PRJ  = S + OFF_PRJ;
    float* SRC  = S + OFF_SRC;
    float* DISP = S + OFF_DISP;
    float* Hb   = S + OFF_H;
    float* Yb   = S + OFF_Y;
    float* TW   = S + OFF_TOPW;
    float* WQKV = S + OFF_WQKV;
    float* BQKV = S + OFF_BQKV;
    int* topi    = I;
    int* slotpos = I + NSLOT;
    int* ecnt    = I + 2 * NSLOT;

    cudaFuncSetAttribute(gemm_tc_kernel<false>,
                         cudaFuncAttributeMaxDynamicSharedMemorySize, GEMM_SMEM_BYTES);
    cudaFuncSetAttribute(gemm_tc_kernel<true>,
                         cudaFuncAttributeMaxDynamicSharedMemorySize, GEMM_SMEM_BYTES);

    dim3 blk(128);

    // pack QKV weights + biases contiguously (graph-capturable async D2D)
    cudaMemcpyAsync(WQKV,              wq, NWPROJ * 4, cudaMemcpyDeviceToDevice);
    cudaMemcpyAsync(WQKV + NWPROJ,     wk, NWPROJ * 4, cudaMemcpyDeviceToDevice);
    cudaMemcpyAsync(WQKV + 2 * NWPROJ, wv, NWPROJ * 4, cudaMemcpyDeviceToDevice);
    cudaMemcpyAsync(BQKV,        bq, Dn * 4, cudaMemcpyDeviceToDevice);
    cudaMemcpyAsync(BQKV + Dn,   bk, Dn * 4, cudaMemcpyDeviceToDevice);
    cudaMemcpyAsync(BQKV + 2*Dn, bv, Dn * 4, cudaMemcpyDeviceToDevice);

    // --- attention block ---
    gemm_tc_kernel<false><<<dim3(Dn / BN, Tn / BM, 3), blk, GEMM_SMEM_BYTES>>>(
        x, Dn, 0,
        WQKV, Dn, NWPROJ,
        BQKV, Dn,
        Qb, Dn, NPROJ,
        Dn, nullptr);
    attn_mma_kernel<<<dim3(Cn / 64, Bn * Hn), 128>>>(Qb, Kbuf, Vb, msk, ATT);
    gemm_tc_kernel<false><<<dim3(Dn / BN, Tn / BM, 1), blk, GEMM_SMEM_BYTES>>>(
        ATT, Dn, 0, wo, Dn, 0, bo, 0, PRJ, Dn, 0, Dn, nullptr);
    add_ln_kernel<<<Tn / 8, 256>>>(x, PRJ, ln1g, ln1b, SRC);

    // --- MoE block ---
    router_kernel<<<Tn / 8, 256>>>(SRC, rw, topi, TW);
    scan_kernel<<<1, 1024>>>(topi, slotpos, ecnt);
    scatter_kernel<<<NSLOT, 64>>>(SRC, topi, slotpos, DISP);

    // batched expert FFN: z = expert index
    gemm_tc_kernel<true><<<dim3(FFn / BN, CAPn / BM, En), blk, GEMM_SMEM_BYTES>>>(
        DISP, Dn, (size_t)CAPn * Dn,
        w1,   FFn, (size_t)Dn * FFn,
        b1,   FFn,
        Hb,   FFn, (size_t)CAPn * FFn,
        Dn, ecnt);
    gemm_tc_kernel<false><<<dim3(Dn / BN, CAPn / BM, En), blk, GEMM_SMEM_BYTES>>>(
        Hb, FFn, (size_t)CAPn * FFn,
        w2, Dn,  (size_t)FFn * Dn,
        b2, Dn,
        Yb, Dn,  (size_t)CAPn * Dn,
        FFn, ecnt);

    combine_ln_kernel<<<Tn / 8, 256>>>(SRC, Yb, topi, TW, slotpos,
                                       ln2g, ln2b, out);
}

// round 15
// speedup vs baseline: 1.0831x; 1.0831x over previous
#include <cuda_runtime.h>
#include <math.h>
#include <stdint.h>

// ---------------------------------------------------------------------------
// Problem constants
// ---------------------------------------------------------------------------
#define Bn    16
#define Cn    1024
#define Dn    512
#define Hn    8
#define HDn   64
#define En    8
#define Ktop  2
#define FFn   2048
#define Tn    (Bn*Cn)        /* 16384 tokens */
#define CAPn  5120
#define NSLOT (Tn*Ktop)      /* 32768 slots  */

// ---------------------------------------------------------------------------
// Scratch (~571 MB; DISP and H regions reused as bf16)
// ---------------------------------------------------------------------------
static constexpr size_t NPROJ    = (size_t)Tn * Dn;
static constexpr size_t OFF_Q    = 0;
static constexpr size_t OFF_K    = 1 * NPROJ;
static constexpr size_t OFF_V    = 2 * NPROJ;
static constexpr size_t OFF_ATTN = 3 * NPROJ;
static constexpr size_t OFF_PRJ  = OFF_Q;
static constexpr size_t OFF_SRC  = OFF_K;
static constexpr size_t OFF_DISP = OFF_V;
static constexpr size_t NDISP    = (size_t)En * CAPn * Dn;
static constexpr size_t OFF_H    = OFF_DISP + NDISP;
static constexpr size_t NH       = (size_t)En * CAPn * FFn;
static constexpr size_t OFF_Y    = OFF_H + NH;
static constexpr size_t OFF_TOPW = OFF_Y + NDISP;
static constexpr size_t SCRATCH_FLOATS = OFF_TOPW + NSLOT;

__device__ float g_scratch[SCRATCH_FLOATS];
__device__ int   g_iscratch[2 * NSLOT + 8];

// ---------------------------------------------------------------------------
static __device__ __forceinline__ float gelu_fn(float x) {
    float x3 = x * x * x;
    float u  = 0.7978845608028654f * (x + 0.044715f * x3);
    return 0.5f * x * (1.0f + tanhf(u));
}

static __device__ __forceinline__ uint32_t f2tf(float x) {
    uint32_t u;
    asm("cvt.rna.tf32.f32 %0, %1;" : "=r"(u) : "f"(x));
    return u;
}

// pack two floats -> bf16x2 reg, lo in bits[0:16) (validated in R9)
static __device__ __forceinline__ uint32_t pack_bf16(float lo, float hi) {
    uint32_t r;
    asm("cvt.rn.bf16x2.f32 %0, %1, %2;" : "=r"(r) : "f"(hi), "f"(lo));
    return r;
}

#define MMA_TF32(acc, a, b0, b1)                                              \
    asm volatile(                                                             \
        "mma.sync.aligned.m16n8k8.row.col.f32.tf32.tf32.f32 "                 \
        "{%0,%1,%2,%3}, {%4,%5,%6,%7}, {%8,%9}, {%0,%1,%2,%3};"               \
        : "+f"(acc[0]), "+f"(acc[1]), "+f"(acc[2]), "+f"(acc[3])              \
        : "r"(a[0]), "r"(a[1]), "r"(a[2]), "r"(a[3]), "r"(b0), "r"(b1))

#define MMA_BF16(acc, a, b0, b1)                                              \
    asm volatile(                                                             \
        "mma.sync.aligned.m16n8k16.row.col.f32.bf16.bf16.f32 "                \
        "{%0,%1,%2,%3}, {%4,%5,%6,%7}, {%8,%9}, {%0,%1,%2,%3};"               \
        : "+f"(acc[0]), "+f"(acc[1]), "+f"(acc[2]), "+f"(acc[3])              \
        : "r"(a[0]), "r"(a[1]), "r"(a[2]), "r"(a[3]), "r"(b0), "r"(b1))

static __device__ __forceinline__ void cp_async16(uint32_t saddr, const void* g) {
    asm volatile("cp.async.cg.shared.global [%0], [%1], 16;" :: "r"(saddr), "l"(g));
}

// ---------------------------------------------------------------------------
// tf32 mma.sync GEMM (R7-exact): 3-stage cp.async, 128 thr, 64x64 warp tile,
// f2tf (rna) at fragment load.  Used for the 4 projection GEMMs.
// ---------------------------------------------------------------------------
#define BM 128
#define BN 128
#define BKt 32
#define ASTRIDE 36
#define BSTRIDE 136
#define ASTAGE (BM * ASTRIDE)
#define BSTAGE (BKt * BSTRIDE)
#define GEMM_SMEM_BYTES ((3 * (ASTAGE + BSTAGE)) * 4)   // 107520

__global__ __launch_bounds__(128) void gemm_tf32_kernel(
    const float* __restrict__ A, int lda,
    const float* __restrict__ Bm, int ldb,
    const float* __restrict__ bias,
    float* __restrict__ C, int ldc, int Kd)
{
    extern __shared__ float dsm[];
    float* Asm = dsm;
    float* Bsm = dsm + 3 * ASTAGE;

    const int tid  = threadIdx.x;
    const int wid  = tid >> 5;
    const int lane = tid & 31;
    const int wm   = (wid & 1) * 64;
    const int wnn  = (wid >> 1) * 64;
    const int g    = lane >> 2;
    const int tg   = lane & 3;

    const int arow = tid >> 3;
    const int acol = (tid & 7) * 4;
    const int brow = tid >> 5;
    const int bcol = (tid & 31) * 4;

    const float* Ag = A + (size_t)(blockIdx.y * BM + arow) * lda + acol;
    const float* Bg = Bm + (size_t)brow * ldb + blockIdx.x * BN + bcol;

    const uint32_t asb = (uint32_t)__cvta_generic_to_shared(Asm) +
                         (arow * ASTRIDE + acol) * 4;
    const uint32_t bsb = (uint32_t)__cvta_generic_to_shared(Bsm) +
                         (brow * BSTRIDE + bcol) * 4;

    const int ntile = Kd / BKt;

#define GEMM_PREFETCH(stage, kt)                                              \
    do {                                                                      \
        const float* ga = Ag + (kt) * BKt;                                    \
        const float* gb = Bg + (size_t)(kt) * BKt * ldb;                      \
        uint32_t sa = asb + (stage) * (ASTAGE * 4);                           \
        uint32_t sb = bsb + (stage) * (BSTAGE * 4);                           \
        _Pragma("unroll")                                                     \
        for (int s = 0; s < 8; s++)                                           \
            cp_async16(sa + s * (16 * ASTRIDE * 4), ga + (size_t)s * 16 * lda);\
        _Pragma("unroll")                                                     \
        for (int s = 0; s < 8; s++)                                           \
            cp_async16(sb + s * (4 * BSTRIDE * 4), gb + (size_t)s * 4 * ldb); \
        asm volatile("cp.async.commit_group;");                               \
    } while (0)

    GEMM_PREFETCH(0, 0);
    if (ntile > 1) GEMM_PREFETCH(1, 1);
    else asm volatile("cp.async.commit_group;");

    float acc[4][8][4];
    #pragma unroll
    for (int i = 0; i < 4; i++)
        #pragma unroll
        for (int j = 0; j < 8; j++) {
            acc[i][j][0] = 0.f; acc[i][j][1] = 0.f;
            acc[i][j][2] = 0.f; acc[i][j][3] = 0.f;
        }

    for (int kt = 0; kt < ntile; kt++) {
        if (kt + 2 < ntile) {
            GEMM_PREFETCH((kt + 2) % 3, kt + 2);
            asm volatile("cp.async.wait_group 2;");
        } else if (kt + 1 < ntile) {
            asm volatile("cp.async.wait_group 1;");
        } else {
            asm volatile("cp.async.wait_group 0;");
        }
        __syncthreads();

        const float* Ab = Asm + (kt % 3) * ASTAGE;
        const float* Bb = Bsm + (kt % 3) * BSTAGE;

        #pragma unroll
        for (int kc = 0; kc < 4; kc++) {
            const int k0 = kc * 8;
            uint32_t afr[4][4];
            #pragma unroll
            for (int i = 0; i < 4; i++) {
                const float* ra = Ab + (wm + i * 16 + g) * ASTRIDE + k0;
                const float* rb = ra + 8 * ASTRIDE;
                afr[i][0] = f2tf(ra[tg]);
                afr[i][1] = f2tf(rb[tg]);
                afr[i][2] = f2tf(ra[tg + 4]);
                afr[i][3] = f2tf(rb[tg + 4]);
            }
            uint32_t bfr[8][2];
            #pragma unroll
            for (int j = 0; j < 8; j++) {
                int n = wnn + j * 8 + g;
                bfr[j][0] = f2tf(Bb[(k0 + tg) * BSTRIDE + n]);
                bfr[j][1] = f2tf(Bb[(k0 + tg + 4) * BSTRIDE + n]);
            }
            #pragma unroll
            for (int i = 0; i < 4; i++)
                #pragma unroll
                for (int j = 0; j < 8; j++)
                    MMA_TF32(acc[i][j], afr[i], bfr[j][0], bfr[j][1]);
        }
        __syncthreads();
    }
#undef GEMM_PREFETCH

    #pragma unroll
    for (int j = 0; j < 8; j++) {
        const int col = blockIdx.x * BN + wnn + j * 8 + 2 * tg;
        const float2 bb = *(const float2*)(bias + col);
        #pragma unroll
        for (int i = 0; i < 4; i++) {
            const size_t row0 = (size_t)blockIdx.y * BM + wm + i * 16 + g;
            float2 v0, v1;
            v0.x = acc[i][j][0] + bb.x;
            v0.y = acc[i][j][1] + bb.y;
            v1.x = acc[i][j][2] + bb.x;
            v1.y = acc[i][j][3] + bb.y;
            *(float2*)(C + row0 * ldc + col)       = v0;
            *(float2*)(C + (row0 + 8) * ldc + col) = v1;
        }
    }
}

// ---------------------------------------------------------------------------
// Expert GEMM, bf16 m16n8k16: A operand bf16-in-smem (direct packed loads --
// halves A crossbar bytes; K-per-MMA doubled), B fp32-in-smem with
// pack-at-load (stride 132, conflict-free per R9).
//   C[z][M,N] = A_bf16[z][M,K] @ B[z][K,N] + bias[z]  (opt GELU, opt bf16 out)
// 128x128x32 tile, 128 threads (4 warps 2x2), warp tile 64x64, 3-stage.
// ---------------------------------------------------------------------------
#define XAW 20                               // A row stride in 32-bit words
#define XABYTES (128 * XAW * 4)              // 10240 B per A stage
#define XBSTR 132
#define XBFLOATS (BKt * XBSTR)               // 4224 floats
#define XBBYTES (XBFLOATS * 4)               // 16896 B per B stage
#define XSMEM_BYTES (3 * (XABYTES + XBBYTES))  // 81408

template <bool GELU, bool OUTBF>
__global__ __launch_bounds__(128) void gemm_bf16a_kernel(
    const uint16_t* __restrict__ A, int lda, size_t aZ,
    const float* __restrict__ Bm, int ldb, size_t bZ,
    const float* __restrict__ bias, int biasZ,
    void* __restrict__ C, int ldc, size_t cZ,
    int Kd, const int* __restrict__ mcount)
{
    const int z = blockIdx.z;
    if (mcount && (int)(blockIdx.y * BM) >= mcount[z]) return;

    extern __shared__ uint8_t xs[];
    const uint32_t abase = (uint32_t)__cvta_generic_to_shared(xs);
    const uint32_t bbase = abase + 3 * XABYTES;

    const int tid  = threadIdx.x;
    const int wid  = tid >> 5;
    const int lane = tid & 31;
    const int wm   = (wid & 1) * 64;
    const int wnn  = (wid >> 1) * 64;
    const int g    = lane >> 2;
    const int tg   = lane & 3;

    // A staging: one row per thread, 4 x 16B chunks (32 bf16 per row)
    const uint16_t* Ag = A + z * aZ + (size_t)(blockIdx.y * BM + tid) * lda;
    // B staging: as R7 but stride 132
    const int brow = tid >> 5;
    const int bcol = (tid & 31) * 4;
    const float* Bg = Bm + z * bZ + (size_t)brow * ldb + blockIdx.x * BN + bcol;
    const uint32_t bsb = bbase + (brow * XBSTR + bcol) * 4;

    const int ntile = Kd / BKt;

#define XPREFETCH(stage, kt)                                                  \
    do {                                                                      \
        const uint16_t* ga = Ag + (kt) * BKt;                                 \
        const float* gb = Bg + (size_t)(kt) * BKt * ldb;                      \
        uint32_t sa = abase + (stage) * XABYTES + tid * (XAW * 4);            \
        uint32_t sb = bsb + (stage) * XBBYTES;                                \
        _Pragma("unroll")                                                     \
        for (int c = 0; c < 4; c++)                                           \
            cp_async16(sa + c * 16, ga + c * 8);                              \
        _Pragma("unroll")                                                     \
        for (int s = 0; s < 8; s++)                                           \
            cp_async16(sb + s * (4 * XBSTR * 4), gb + (size_t)s * 4 * ldb);   \
        asm volatile("cp.async.commit_group;");                               \
    } while (0)

    XPREFETCH(0, 0);
    if (ntile > 1) XPREFETCH(1, 1);
    else asm volatile("cp.async.commit_group;");

    float acc[4][8][4];
    #pragma unroll
    for (int i = 0; i < 4; i++)
        #pragma unroll
        for (int j = 0; j < 8; j++) {
            acc[i][j][0] = 0.f; acc[i][j][1] = 0.f;
            acc[i][j][2] = 0.f; acc[i][j][3] = 0.f;
        }

    for (int kt = 0; kt < ntile; kt++) {
        if (kt + 2 < ntile) {
            XPREFETCH((kt + 2) % 3, kt + 2);
            asm volatile("cp.async.wait_group 2;");
        } else if (kt + 1 < ntile) {
            asm volatile("cp.async.wait_group 1;");
        } else {
            asm volatile("cp.async.wait_group 0;");
        }
        __syncthreads();

        const uint32_t* Aw = (const uint32_t*)(xs + (kt % 3) * XABYTES);
        const float*    Bb = (const float*)(xs + 3 * XABYTES + (kt % 3) * XBBYTES);

        #pragma unroll
        for (int kc = 0; kc < 2; kc++) {
            const int kw = kc * 8;          // word offset into A row
            const int kbase = kc * 16;      // float row offset into B
            uint32_t afr[4][4];
            #pragma unroll
            for (int i = 0; i < 4; i++) {
                const uint32_t* ra = Aw + (wm + i * 16 + g) * XAW + kw;
                const uint32_t* rb = ra + 8 * XAW;
                afr[i][0] = ra[tg];
                afr[i][1] = rb[tg];
                afr[i][2] = ra[tg + 4];
                afr[i][3] = rb[tg + 4];
            }
            uint32_t bfr[8][2];
            #pragma unroll
            for (int j = 0; j < 8; j++) {
                const float* rk = Bb + (kbase + 2 * tg) * XBSTR + wnn + j * 8 + g;
                bfr[j][0] = pack_bf16(rk[0],            rk[XBSTR]);
                bfr[j][1] = pack_bf16(rk[8 * XBSTR],    rk[9 * XBSTR]);
            }
            #pragma unroll
            for (int i = 0; i < 4; i++)
                #pragma unroll
                for (int j = 0; j < 8; j++)
                    MMA_BF16(acc[i][j], afr[i], bfr[j][0], bfr[j][1]);
        }
        __syncthreads();
    }
#undef XPREFETCH

    // epilogue
    const float* bz = bias + (size_t)z * biasZ;
    #pragma unroll
    for (int j = 0; j < 8; j++) {
        const int col = blockIdx.x * BN + wnn + j * 8 + 2 * tg;
        const float2 bb = *(const float2*)(bz + col);
        #pragma unroll
        for (int i = 0; i < 4; i++) {
            const size_t row0 = (size_t)blockIdx.y * BM + wm + i * 16 + g;
            float2 v0, v1;
            v0.x = acc[i][j][0] + bb.x;
            v0.y = acc[i][j][1] + bb.y;
            v1.x = acc[i][j][2] + bb.x;
            v1.y = acc[i][j][3] + bb.y;
            if (GELU) {
                v0.x = gelu_fn(v0.x); v0.y = gelu_fn(v0.y);
                v1.x = gelu_fn(v1.x); v1.y = gelu_fn(v1.y);
            }
            if (OUTBF) {
                uint16_t* Cz = (uint16_t*)C + z * cZ;
                *(uint32_t*)(Cz + row0 * ldc + col)       = pack_bf16(v0.x, v0.y);
                *(uint32_t*)(Cz + (row0 + 8) * ldc + col) = pack_bf16(v1.x, v1.y);
            } else {
                float* Cz = (float*)C + z * cZ;
                *(float2*)(Cz + row0 * ldc + col)       = v0;
                *(float2*)(Cz + (row0 + 8) * ldc + col) = v1;
            }
        }
    }
}

// ---------------------------------------------------------------------------
// Flash attention, tf32 tensor cores (R7-exact).
// ---------------------------------------------------------------------------
__global__ __launch_bounds__(128) void attn_mma_kernel(
    const float* __restrict__ Q, const float* __restrict__ Kb,
    const float* __restrict__ V, const int* __restrict__ mask,
    float* __restrict__ O)
{
    __shared__ uint32_t sK[64][68];
    __shared__ uint32_t sV[64][72];
    __shared__ uint32_t sP[4][16][36];
    __shared__ int      sM[64];

    const int tid  = threadIdx.x;
    const int w    = tid >> 5;
    const int lane = tid & 31;
    const int g    = lane >> 2;
    const int tg   = lane & 3;

    const int bh = blockIdx.y;
    const int b  = bh >> 3, h = bh & 7;
    const int q0 = blockIdx.x << 6;
    const size_t rowbase = (size_t)b * Cn;

    const float* QB = Q  + (rowbase + q0) * Dn + h * HDn;
    const float* KB = Kb + rowbase * Dn + h * HDn;
    const float* VB = V  + rowbase * Dn + h * HDn;
    const int*   MB = mask + b * Cn;

    #pragma unroll
    for (int i = 0; i < 8; i++) {
        int slot = tid + i * 128;
        int r = slot >> 4, c4 = (slot & 15) << 2;
        float4 qv = *(const float4*)(QB + (size_t)r * Dn + c4);
        sK[r][c4 + 0] = f2tf(qv.x * 0.125f);
        sK[r][c4 + 1] = f2tf(qv.y * 0.125f);
        sK[r][c4 + 2] = f2tf(qv.z * 0.125f);
        sK[r][c4 + 3] = f2tf(qv.w * 0.125f);
    }
    __syncthreads();

    const int row0 = w * 16 + g;
    uint32_t qa[8][4];
    #pragma unroll
    for (int ks = 0; ks < 8; ks++) {
        qa[ks][0] = sK[row0][8 * ks + tg];
        qa[ks][1] = sK[row0 + 8][8 * ks + tg];
        qa[ks][2] = sK[row0][8 * ks + tg + 4];
        qa[ks][3] = sK[row0 + 8][8 * ks + tg + 4];
    }
    __syncthreads();

    float o[8][4];
    #pragma unroll
    for (int jn = 0; jn < 8; jn++) {
        o[jn][0] = 0.f; o[jn][1] = 0.f; o[jn][2] = 0.f; o[jn][3] = 0.f;
    }
    float mrun0 = -3.0e38f, mrun1 = -3.0e38f;
    float lrun0 = 0.f, lrun1 = 0.f;

    for (int kt = 0; kt < Cn / 64; kt++) {
        const int k0 = kt * 64;
        #pragma unroll
        for (int i = 0; i < 8; i++) {
            int slot = tid + i * 128;
            int r = slot >> 4, c4 = (slot & 15) << 2;
            float4 kv = *(const float4*)(KB + (size_t)(k0 + r) * Dn + c4);
            float4 vv = *(const float4*)(VB + (size_t)(k0 + r) * Dn + c4);
            sK[r][c4 + 0] = f2tf(kv.x); sK[r][c4 + 1] = f2tf(kv.y);
            sK[r][c4 + 2] = f2tf(kv.z); sK[r][c4 + 3] = f2tf(kv.w);
            sV[r][c4 + 0] = f2tf(vv.x); sV[r][c4 + 1] = f2tf(vv.y);
            sV[r][c4 + 2] = f2tf(vv.z); sV[r][c4 + 3] = f2tf(vv.w);
        }
        if (tid < 64) sM[tid] = MB[k0 + tid];
        __syncthreads();

        #pragma unroll
        for (int kc = 0; kc < 2; kc++) {
            float sacc[4][4];
            #pragma unroll
            for (int j = 0; j < 4; j++) {
                sacc[j][0] = 0.f; sacc[j][1] = 0.f;
                sacc[j][2] = 0.f; sacc[j][3] = 0.f;
            }
            #pragma unroll
            for (int ks = 0; ks < 8; ks++) {
                #pragma unroll
                for (int j = 0; j < 4; j++) {
                    int n = kc * 32 + 8 * j + g;
                    uint32_t b0 = sK[n][8 * ks + tg];
                    uint32_t b1 = sK[n][8 * ks + tg + 4];
                    MMA_TF32(sacc[j], qa[ks], b0, b1);
                }
            }

            #pragma unroll
            for (int j = 0; j < 4; j++) {
                int c = kc * 32 + 8 * j + 2 * tg;
                if (sM[c] == 0)     { sacc[j][0] = -1e10f; sacc[j][2] = -1e10f; }
                if (sM[c + 1] == 0) { sacc[j][1] = -1e10f; sacc[j][3] = -1e10f; }
            }

            float mx0 = -3.0e38f, mx1 = -3.0e38f;
            #pragma unroll
            for (int j = 0; j < 4; j++) {
                mx0 = fmaxf(mx0, fmaxf(sacc[j][0], sacc[j][1]));
                mx1 = fmaxf(mx1, fmaxf(sacc[j][2], sacc[j][3]));
            }
            mx0 = fmaxf(mx0, __shfl_xor_sync(0xffffffffu, mx0, 1));
            mx0 = fmaxf(mx0, __shfl_xor_sync(0xffffffffu, mx0, 2));
            mx1 = fmaxf(mx1, __shfl_xor_sync(0xffffffffu, mx1, 1));
            mx1 = fmaxf(mx1, __shfl_xor_sync(0xffffffffu, mx1, 2));

            float mnew0 = fmaxf(mrun0, mx0);
            float mnew1 = fmaxf(mrun1, mx1);
            float corr0 = __expf(mrun0 - mnew0);
            float corr1 = __expf(mrun1 - mnew1);
            mrun0 = mnew0; mrun1 = mnew1;

            float p[4][4];
            float ls0 = 0.f, ls1 = 0.f;
            #pragma unroll
            for (int j = 0; j < 4; j++) {
                p[j][0] = __expf(sacc[j][0] - mnew0);
                p[j][1] = __expf(sacc[j][1] - mnew0);
                p[j][2] = __expf(sacc[j][2] - mnew1);
                p[j][3] = __expf(sacc[j][3] - mnew1);
                ls0 += p[j][0] + p[j][1];
                ls1 += p[j][2] + p[j][3];
            }
            ls0 += __shfl_xor_sync(0xffffffffu, ls0, 1);
            ls0 += __shfl_xor_sync(0xffffffffu, ls0, 2);
            ls1 += __shfl_xor_sync(0xffffffffu, ls1, 1);
            ls1 += __shfl_xor_sync(0xffffffffu, ls1, 2);
            lrun0 = lrun0 * corr0 + ls0;
            lrun1 = lrun1 * corr1 + ls1;

            #pragma unroll
            for (int jn = 0; jn < 8; jn++) {
                o[jn][0] *= corr0; o[jn][1] *= corr0;
                o[jn][2] *= corr1; o[jn][3] *= corr1;
            }

            #pragma unroll
            for (int j = 0; j < 4; j++) {
                int c = 8 * j + 2 * tg;
                sP[w][g][c]         = f2tf(p[j][0]);
                sP[w][g][c + 1]     = f2tf(p[j][1]);
                sP[w][g + 8][c]     = f2tf(p[j][2]);
                sP[w][g + 8][c + 1] = f2tf(p[j][3]);
            }
            __syncwarp();

            uint32_t pa[4][4];
            #pragma unroll
            for (int ks = 0; ks < 4; ks++) {
                pa[ks][0] = sP[w][g][8 * ks + tg];
                pa[ks][1] = sP[w][g + 8][8 * ks + tg];
                pa[ks][2] = sP[w][g][8 * ks + tg + 4];
                pa[ks][3] = sP[w][g + 8][8 * ks + tg + 4];
            }
            __syncwarp();

            #pragma unroll
            for (int ks = 0; ks < 4; ks++) {
                int kr = kc * 32 + 8 * ks;
                #pragma unroll
                for (int jn = 0; jn < 8; jn++) {
                    uint32_t b0 = sV[kr + tg][8 * jn + g];
                    uint32_t b1 = sV[kr + tg + 4][8 * jn + g];
                    MMA_TF32(o[jn], pa[ks], b0, b1);
                }
            }
        }
        __syncthreads();
    }

    const float inv0 = 1.0f / lrun0;
    const float inv1 = 1.0f / lrun1;
    const size_t grow = rowbase + q0 + row0;
    #pragma unroll
    for (int jn = 0; jn < 8; jn++) {
        int col = h * HDn + 8 * jn + 2 * tg;
        float2 v0, v1;
        v0.x = o[jn][0] * inv0; v0.y = o[jn][1] * inv0;
        v1.x = o[jn][2] * inv1; v1.y = o[jn][3] * inv1;
        *(float2*)(O + grow * Dn + col)       = v0;
        *(float2*)(O + (grow + 8) * Dn + col) = v1;
    }
}

// ---------------------------------------------------------------------------
// Residual add + LayerNorm (R7).
// ---------------------------------------------------------------------------
__global__ __launch_bounds__(256) void add_ln_kernel(
    const float* __restrict__ A, const float* __restrict__ R,
    const float* __restrict__ gam, const float* __restrict__ bet,
    float* __restrict__ out)
{
    int w    = (blockIdx.x * 256 + threadIdx.x) >> 5;
    int lane = threadIdx.x & 31;
    const float4* a4 = (const float4*)(A + (size_t)w * Dn);
    const float4* r4 = (const float4*)(R + (size_t)w * Dn);
    float4 v[4];
    float s = 0.0f, s2 = 0.0f;
    #pragma unroll
    for (int i = 0; i < 4; i++) {
        float4 xa = a4[lane + i * 32], xr = r4[lane + i * 32];
        v[i].x = xa.x + xr.x; v[i].y = xa.y + xr.y;
        v[i].z = xa.z + xr.z; v[i].w = xa.w + xr.w;
        s  += v[i].x + v[i].y + v[i].z + v[i].w;
        s2 += v[i].x * v[i].x + v[i].y * v[i].y + v[i].z * v[i].z + v[i].w * v[i].w;
    }
    #pragma unroll
    for (int off = 16; off; off >>= 1) {
        s  += __shfl_xor_sync(0xffffffffu, s,  off);
        s2 += __shfl_xor_sync(0xffffffffu, s2, off);
    }
    float mean = s * (1.0f / Dn);
    float var  = s2 * (1.0f / Dn) - mean * mean;
    float inv  = rsqrtf(var + 1e-5f);
    const float4* g4 = (const float4*)gam;
    const float4* b4 = (const float4*)bet;
    float4* o4 = (float4*)(out + (size_t)w * Dn);
    #pragma unroll
    for (int i = 0; i < 4; i++) {
        float4 g = g4[lane + i * 32], be = b4[lane + i * 32];
        float4 r;
        r.x = (v[i].x - mean) * inv * g.x + be.x;
        r.y = (v[i].y - mean) * inv * g.y + be.y;
        r.z = (v[i].z - mean) * inv * g.z + be.z;
        r.w = (v[i].w - mean) * inv * g.w + be.w;
        o4[lane + i * 32] = r;
    }
}

// ---------------------------------------------------------------------------
// Router (R7).
// ---------------------------------------------------------------------------
__global__ __launch_bounds__(256) void router_kernel(
    const float* __restrict__ src, const float* __restrict__ rw,
    int* __restrict__ topi, float* __restrict__ topw)
{
    int w    = (blockIdx.x * 256 + threadIdx.x) >> 5;
    int lane = threadIdx.x & 31;
    const float* xr = src + (size_t)w * Dn;
    float acc[8] = {0, 0, 0, 0, 0, 0, 0, 0};
    for (int d = lane; d < Dn; d += 32) {
        float xv = xr[d];
        const float4* r4 = (const float4*)(rw + d * 8);
        float4 r0 = r4[0], r1 = r4[1];
        acc[0] += xv * r0.x; acc[1] += xv * r0.y; acc[2] += xv * r0.z; acc[3] += xv * r0.w;
        acc[4] += xv * r1.x; acc[5] += xv * r1.y; acc[6] += xv * r1.z; acc[7] += xv * r1.w;
    }
    #pragma unroll
    for (int e = 0; e < 8; e++)
        #pragma unroll
        for (int off = 16; off; off >>= 1)
            acc[e] += __shfl_xor_sync(0xffffffffu, acc[e], off);

    if (lane == 0) {
        float mx = acc[0];
        #pragma unroll
        for (int e = 1; e < 8; e++) mx = fmaxf(mx, acc[e]);
        float pe[8], sum = 0.0f;
        #pragma unroll
        for (int e = 0; e < 8; e++) { pe[e] = __expf(acc[e] - mx); sum += pe[e]; }
        float isum = 1.0f / sum;
        #pragma unroll
        for (int e = 0; e < 8; e++) pe[e] *= isum;
        int i1 = 0; float v1 = pe[0];
        #pragma unroll
        for (int e = 1; e < 8; e++) if (pe[e] > v1) { v1 = pe[e]; i1 = e; }
        int i2 = -1; float v2 = -1.0f;
        #pragma unroll
        for (int e = 0; e < 8; e++) if (e != i1 && pe[e] > v2) { v2 = pe[e]; i2 = e; }
        float wn = 1.0f / (v1 + v2);
        topi[2 * w]     = i1;  topi[2 * w + 1] = i2;
        topw[2 * w]     = v1 * wn;  topw[2 * w + 1] = v2 * wn;
    }
}

// ---------------------------------------------------------------------------
// Deterministic capacity scan (unchanged).
// ---------------------------------------------------------------------------
__global__ __launch_bounds__(1024) void scan_kernel(
    const int* __restrict__ topi, int* __restrict__ slotpos,
    int* __restrict__ ecnt)
{
    __shared__ int wtot[32][8];
    __shared__ int wbase[32][8];
    int tid = threadIdx.x, lane = tid & 31, wid = tid >> 5;
    int base = tid * 32;

    int eid[32];
    #pragma unroll
    for (int i = 0; i < 32; i++) eid[i] = topi[base + i];

    int c[8];
    #pragma unroll
    for (int e = 0; e < 8; e++) {
        int ce = 0;
        #pragma unroll
        for (int i = 0; i < 32; i++) ce += (eid[i] == e);
        c[e] = ce;
    }

    int inc[8], excl[8];
    #pragma unroll
    for (int e = 0; e < 8; e++) {
        int v = c[e];
        for (int off = 1; off < 32; off <<= 1) {
            int n = __shfl_up_sync(0xffffffffu, v, off);
            if (lane >= off) v += n;
        }
        inc[e] = v; excl[e] = v - c[e];
    }
    if (lane == 31) {
        #pragma unroll
        for (int e = 0; e < 8; e++) wtot[wid][e] = inc[e];
    }
    __syncthreads();
    if (wid == 0) {
        #pragma unroll
        for (int e = 0; e < 8; e++) {
            int t = wtot[lane][e];
            int v = t;
            for (int off = 1; off < 32; off <<= 1) {
                int n = __shfl_up_sync(0xffffffffu, v, off);
                if (lane >= off) v += n;
            }
            wbase[lane][e] = v - t;
            if (lane == 31) ecnt[e] = min(v, CAPn);
        }
    }
    __syncthreads();

    int run[8];
    #pragma unroll
    for (int e = 0; e < 8; e++) run[e] = wbase[wid][e] + excl[e];

    #pragma unroll
    for (int i = 0; i < 32; i++) {
        int e = eid[i];
        int p = 0;
        #pragma unroll
        for (int ee = 0; ee < 8; ee++)
            if (e == ee) { p = run[ee]; run[ee] = p + 1; }
        slotpos[base + i] = (p < CAPn) ? p : -1;
    }
}

// ---------------------------------------------------------------------------
// Scatter kept slots into disp[E, CAP, D] as bf16 (feeds bf16 expert GEMM).
// ---------------------------------------------------------------------------
__global__ __launch_bounds__(64) void scatter_kernel(
    const float* __restrict__ src, const int* __restrict__ topi,
    const int* __restrict__ slotpos, uint16_t* __restrict__ disp)
{
    int s = blockIdx.x;
    int p = slotpos[s];
    if (p < 0) return;
    int e   = topi[s];
    int tok = s >> 1;
    const float4* in4 = (const float4*)(src + (size_t)tok * Dn);
    uint2* out = (uint2*)(disp + ((size_t)e * CAPn + p) * Dn);
    int t = threadIdx.x;
    #pragma unroll
    for (int half = 0; half < 2; half++) {
        float4 v = in4[t + half * 64];
        uint2 u;
        u.x = pack_bf16(v.x, v.y);
        u.y = pack_bf16(v.z, v.w);
        out[t + half * 64] = u;
    }
}

// ---------------------------------------------------------------------------
// Combine + LN2 (unchanged).
// ---------------------------------------------------------------------------
__global__ __launch_bounds__(256) void combine_ln_kernel(
    const float* __restrict__ src, const float* __restrict__ y,
    const int* __restrict__ topi, const float* __restrict__ topw,
    const int* __restrict__ slotpos,
    const float* __restrict__ gam, const float* __restrict__ bet,
    float* __restrict__ out)
{
    int w    = (blockIdx.x * 256 + threadIdx.x) >> 5;
    int lane = threadIdx.x & 31;
    const float4* s4 = (const float4*)(src + (size_t)w * Dn);
    float4 v[4];
    #pragma unroll
    for (int i = 0; i < 4; i++) v[i] = s4[lane + i * 32];

    #pragma unroll
    for (int kk = 0; kk < 2; kk++) {
        int slot = 2 * w + kk;
        int p = slotpos[slot];
        if (p >= 0) {
            int e = topi[slot];
            float ww = topw[slot];
            const float4* y4 = (const float4*)(y + ((size_t)e * CAPn + p) * Dn);
            #pragma unroll
            for (int i = 0; i < 4; i++) {
                float4 yy = y4[lane + i * 32];
                v[i].x += ww * yy.x; v[i].y += ww * yy.y;
                v[i].z += ww * yy.z; v[i].w += ww * yy.w;
            }
        }
    }

    float s = 0.0f, s2 = 0.0f;
    #pragma unroll
    for (int i = 0; i < 4; i++) {
        s  += v[i].x + v[i].y + v[i].z + v[i].w;
        s2 += v[i].x * v[i].x + v[i].y * v[i].y + v[i].z * v[i].z + v[i].w * v[i].w;
    }
    #pragma unroll
    for (int off = 16; off; off >>= 1) {
        s  += __shfl_xor_sync(0xffffffffu, s,  off);
        s2 += __shfl_xor_sync(0xffffffffu, s2, off);
    }
    float mean = s * (1.0f / Dn);
    float var  = s2 * (1.0f / Dn) - mean * mean;
    float inv  = rsqrtf(var + 1e-5f);
    const float4* g4 = (const float4*)gam;
    const float4* b4 = (const float4*)bet;
    float4* o4 = (float4*)(out + (size_t)w * Dn);
    #pragma unroll
    for (int i = 0; i < 4; i++) {
        float4 g = g4[lane + i * 32], be = b4[lane + i * 32];
        float4 r;
        r.x = (v[i].x - mean) * inv * g.x + be.x;
        r.y = (v[i].y - mean) * inv * g.y + be.y;
        r.z = (v[i].z - mean) * inv * g.z + be.z;
        r.w = (v[i].w - mean) * inv * g.w + be.w;
        o4[lane + i * 32] = r;
    }
}

// ---------------------------------------------------------------------------
// Launch sequence
// ---------------------------------------------------------------------------
extern "C" void kernel_launch(void* const* d_in, const int* in_sizes, int n_in,
                              void* d_out, int out_size)
{
    const float* x    = (const float*)d_in[0];
    const int*   msk  = (const int*)  d_in[1];
    const float* wq   = (const float*)d_in[2];
    const float* bq   = (const float*)d_in[3];
    const float* wk   = (const float*)d_in[4];
    const float* bk   = (const float*)d_in[5];
    const float* wv   = (const float*)d_in[6];
    const float* bv   = (const float*)d_in[7];
    const float* wo   = (const float*)d_in[8];
    const float* bo   = (const float*)d_in[9];
    const float* ln1g = (const float*)d_in[10];
    const float* ln1b = (const float*)d_in[11];
    const float* ln2g = (const float*)d_in[12];
    const float* ln2b = (const float*)d_in[13];
    const float* rw   = (const float*)d_in[14];
    const float* w1   = (const float*)d_in[15];
    const float* b1   = (const float*)d_in[16];
    const float* w2   = (const float*)d_in[17];
    const float* b2   = (const float*)d_in[18];
    float* out = (float*)d_out;

    float* S = nullptr;
    int*   I = nullptr;
    cudaGetSymbolAddress((void**)&S, g_scratch);
    cudaGetSymbolAddress((void**)&I, g_iscratch);

    float* Qb   = S + OFF_Q;
    float* Kbuf = S + OFF_K;
    float* Vb   = S + OFF_V;
    float* ATT  = S + OFF_ATTN;
    float* PRJ  = S + OFF_PRJ;
    float* SRC  = S + OFF_SRC;
    uint16_t* DISP = (uint16_t*)(S + OFF_DISP);   // bf16 view
    uint16_t* Hb   = (uint16_t*)(S + OFF_H);      // bf16 view
    float* Yb   = S + OFF_Y;
    float* TW   = S + OFF_TOPW;
    int* topi    = I;
    int* slotpos = I + NSLOT;
    int* ecnt    = I + 2 * NSLOT;

    cudaFuncSetAttribute(gemm_tf32_kernel,
                         cudaFuncAttributeMaxDynamicSharedMemorySize, GEMM_SMEM_BYTES);
    cudaFuncSetAttribute(gemm_bf16a_kernel<true, true>,
                         cudaFuncAttributeMaxDynamicSharedMemorySize, XSMEM_BYTES);
    cudaFuncSetAttribute(gemm_bf16a_kernel<false, false>,
                         cudaFuncAttributeMaxDynamicSharedMemorySize, XSMEM_BYTES);

    dim3 blk(128);
    dim3 gproj(Dn / BN, Tn / BM);

    // --- attention block (R7-exact) ---
    gemm_tf32_kernel<<<gproj, blk, GEMM_SMEM_BYTES>>>(x, Dn, wq, Dn, bq, Qb, Dn, Dn);
    gemm_tf32_kernel<<<gproj, blk, GEMM_SMEM_BYTES>>>(x, Dn, wk, Dn, bk, Kbuf, Dn, Dn);
    gemm_tf32_kernel<<<gproj, blk, GEMM_SMEM_BYTES>>>(x, Dn, wv, Dn, bv, Vb, Dn, Dn);
    attn_mma_kernel<<<dim3(Cn / 64, Bn * Hn), 128>>>(Qb, Kbuf, Vb, msk, ATT);
    gemm_tf32_kernel<<<gproj, blk, GEMM_SMEM_BYTES>>>(ATT, Dn, wo, Dn, bo, PRJ, Dn, Dn);
    add_ln_kernel<<<Tn / 8, 256>>>(x, PRJ, ln1g, ln1b, SRC);

    // --- MoE block ---
    router_kernel<<<Tn / 8, 256>>>(SRC, rw, topi, TW);
    scan_kernel<<<1, 1024>>>(topi, slotpos, ecnt);
    scatter_kernel<<<NSLOT, 64>>>(SRC, topi, slotpos, DISP);

    // batched expert FFN (bf16-A m16n8k16): z = expert index
    gemm_bf16a_kernel<true, true><<<dim3(FFn / BN, CAPn / BM, En), blk, XSMEM_BYTES>>>(
        DISP, Dn, (size_t)CAPn * Dn,
        w1,   FFn, (size_t)Dn * FFn,
        b1,   FFn,
        Hb,   FFn, (size_t)CAPn * FFn,
        Dn, ecnt);
    gemm_bf16a_kernel<false, false><<<dim3(Dn / BN, CAPn / BM, En), blk, XSMEM_BYTES>>>(
        Hb, FFn, (size_t)CAPn * FFn,
        w2, Dn,  (size_t)FFn * Dn,
        b2, Dn,
        Yb, Dn,  (size_t)CAPn * Dn,
        FFn, ecnt);

    combine_ln_kernel<<<Tn / 8, 256>>>(SRC, Yb, topi, TW, slotpos,
                                       ln2g, ln2b, out);
}

// round 16
// speedup vs baseline: 1.1427x; 1.0550x over previous
#include <cuda_runtime.h>
#include <math.h>
#include <stdint.h>

// ---------------------------------------------------------------------------
// Problem constants
// ---------------------------------------------------------------------------
#define Bn    16
#define Cn    1024
#define Dn    512
#define Hn    8
#define HDn   64
#define En    8
#define Ktop  2
#define FFn   2048
#define Tn    (Bn*Cn)        /* 16384 tokens */
#define CAPn  5120
#define NSLOT (Tn*Ktop)      /* 32768 slots  */

// ---------------------------------------------------------------------------
// Scratch (~605 MB; DISP/H as bf16; packed bf16 expert weights)
// ---------------------------------------------------------------------------
static constexpr size_t NPROJ    = (size_t)Tn * Dn;
static constexpr size_t OFF_Q    = 0;
static constexpr size_t OFF_K    = 1 * NPROJ;
static constexpr size_t OFF_V    = 2 * NPROJ;
static constexpr size_t OFF_ATTN = 3 * NPROJ;
static constexpr size_t OFF_PRJ  = OFF_Q;
static constexpr size_t OFF_SRC  = OFF_K;
static constexpr size_t OFF_DISP = OFF_V;
static constexpr size_t NDISP    = (size_t)En * CAPn * Dn;
static constexpr size_t OFF_H    = OFF_DISP + NDISP;
static constexpr size_t NH       = (size_t)En * CAPn * FFn;
static constexpr size_t OFF_Y    = OFF_H + NH;
static constexpr size_t OFF_TOPW = OFF_Y + NDISP;
static constexpr size_t NWEXP    = (size_t)En * Dn * FFn;     // 8,388,608
static constexpr size_t OFF_W1P  = OFF_TOPW + NSLOT;          // NWEXP/2 words
static constexpr size_t OFF_W2P  = OFF_W1P + NWEXP / 2;
static constexpr size_t SCRATCH_FLOATS = OFF_W2P + NWEXP / 2;

__device__ float g_scratch[SCRATCH_FLOATS];
__device__ int   g_iscratch[2 * NSLOT + 8];

// ---------------------------------------------------------------------------
static __device__ __forceinline__ float gelu_fn(float x) {
    float x3 = x * x * x;
    float u  = 0.7978845608028654f * (x + 0.044715f * x3);
    return 0.5f * x * (1.0f + tanhf(u));
}

static __device__ __forceinline__ uint32_t f2tf(float x) {
    uint32_t u;
    asm("cvt.rna.tf32.f32 %0, %1;" : "=r"(u) : "f"(x));
    return u;
}

// pack two floats -> bf16x2 reg, lo in bits[0:16) (validated R9/R15)
static __device__ __forceinline__ uint32_t pack_bf16(float lo, float hi) {
    uint32_t r;
    asm("cvt.rn.bf16x2.f32 %0, %1, %2;" : "=r"(r) : "f"(hi), "f"(lo));
    return r;
}

#define MMA_TF32(acc, a, b0, b1)                                              \
    asm volatile(                                                             \
        "mma.sync.aligned.m16n8k8.row.col.f32.tf32.tf32.f32 "                 \
        "{%0,%1,%2,%3}, {%4,%5,%6,%7}, {%8,%9}, {%0,%1,%2,%3};"               \
        : "+f"(acc[0]), "+f"(acc[1]), "+f"(acc[2]), "+f"(acc[3])              \
        : "r"(a[0]), "r"(a[1]), "r"(a[2]), "r"(a[3]), "r"(b0), "r"(b1))

#define MMA_BF16(acc, a, b0, b1)                                              \
    asm volatile(                                                             \
        "mma.sync.aligned.m16n8k16.row.col.f32.bf16.bf16.f32 "                \
        "{%0,%1,%2,%3}, {%4,%5,%6,%7}, {%8,%9}, {%0,%1,%2,%3};"               \
        : "+f"(acc[0]), "+f"(acc[1]), "+f"(acc[2]), "+f"(acc[3])              \
        : "r"(a[0]), "r"(a[1]), "r"(a[2]), "r"(a[3]), "r"(b0), "r"(b1))

static __device__ __forceinline__ void cp_async16(uint32_t saddr, const void* g) {
    asm volatile("cp.async.cg.shared.global [%0], [%1], 16;" :: "r"(saddr), "l"(g));
}

// ---------------------------------------------------------------------------
// Weight pre-pack: wp[kp*N + n] = bf16x2(w[2kp*N + n], w[(2kp+1)*N + n]).
// Identity: 2kp*N + n = idx + kp*N where idx = kp*N + n.
// ---------------------------------------------------------------------------
__global__ __launch_bounds__(256) void pack_w_kernel(
    const float* __restrict__ w, uint32_t* __restrict__ wp,
    int N, size_t nwords)
{
    size_t idx = (size_t)blockIdx.x * 256 + threadIdx.x;
    size_t stride = (size_t)gridDim.x * 256;
    for (; idx < nwords; idx += stride) {
        size_t kp = idx / N;
        float lo = w[idx + kp * N];
        float hi = w[idx + kp * N + N];
        wp[idx] = pack_bf16(lo, hi);
    }
}

// ---------------------------------------------------------------------------
// tf32 mma.sync GEMM (R7-exact).  Used for the 4 projection GEMMs.
// ---------------------------------------------------------------------------
#define BM 128
#define BN 128
#define BKt 32
#define ASTRIDE 36
#define BSTRIDE 136
#define ASTAGE (BM * ASTRIDE)
#define BSTAGE (BKt * BSTRIDE)
#define GEMM_SMEM_BYTES ((3 * (ASTAGE + BSTAGE)) * 4)   // 107520

__global__ __launch_bounds__(128) void gemm_tf32_kernel(
    const float* __restrict__ A, int lda,
    const float* __restrict__ Bm, int ldb,
    const float* __restrict__ bias,
    float* __restrict__ C, int ldc, int Kd)
{
    extern __shared__ float dsm[];
    float* Asm = dsm;
    float* Bsm = dsm + 3 * ASTAGE;

    const int tid  = threadIdx.x;
    const int wid  = tid >> 5;
    const int lane = tid & 31;
    const int wm   = (wid & 1) * 64;
    const int wnn  = (wid >> 1) * 64;
    const int g    = lane >> 2;
    const int tg   = lane & 3;

    const int arow = tid >> 3;
    const int acol = (tid & 7) * 4;
    const int brow = tid >> 5;
    const int bcol = (tid & 31) * 4;

    const float* Ag = A + (size_t)(blockIdx.y * BM + arow) * lda + acol;
    const float* Bg = Bm + (size_t)brow * ldb + blockIdx.x * BN + bcol;

    const uint32_t asb = (uint32_t)__cvta_generic_to_shared(Asm) +
                         (arow * ASTRIDE + acol) * 4;
    const uint32_t bsb = (uint32_t)__cvta_generic_to_shared(Bsm) +
                         (brow * BSTRIDE + bcol) * 4;

    const int ntile = Kd / BKt;

#define GEMM_PREFETCH(stage, kt)                                              \
    do {                                                                      \
        const float* ga = Ag + (kt) * BKt;                                    \
        const float* gb = Bg + (size_t)(kt) * BKt * ldb;                      \
        uint32_t sa = asb + (stage) * (ASTAGE * 4);                           \
        uint32_t sb = bsb + (stage) * (BSTAGE * 4);                           \
        _Pragma("unroll")                                                     \
        for (int s = 0; s < 8; s++)                                           \
            cp_async16(sa + s * (16 * ASTRIDE * 4), ga + (size_t)s * 16 * lda);\
        _Pragma("unroll")                                                     \
        for (int s = 0; s < 8; s++)                                           \
            cp_async16(sb + s * (4 * BSTRIDE * 4), gb + (size_t)s * 4 * ldb); \
        asm volatile("cp.async.commit_group;");                               \
    } while (0)

    GEMM_PREFETCH(0, 0);
    if (ntile > 1) GEMM_PREFETCH(1, 1);
    else asm volatile("cp.async.commit_group;");

    float acc[4][8][4];
    #pragma unroll
    for (int i = 0; i < 4; i++)
        #pragma unroll
        for (int j = 0; j < 8; j++) {
            acc[i][j][0] = 0.f; acc[i][j][1] = 0.f;
            acc[i][j][2] = 0.f; acc[i][j][3] = 0.f;
        }

    for (int kt = 0; kt < ntile; kt++) {
        if (kt + 2 < ntile) {
            GEMM_PREFETCH((kt + 2) % 3, kt + 2);
            asm volatile("cp.async.wait_group 2;");
        } else if (kt + 1 < ntile) {
            asm volatile("cp.async.wait_group 1;");
        } else {
            asm volatile("cp.async.wait_group 0;");
        }
        __syncthreads();

        const float* Ab = Asm + (kt % 3) * ASTAGE;
        const float* Bb = Bsm + (kt % 3) * BSTAGE;

        #pragma unroll
        for (int kc = 0; kc < 4; kc++) {
            const int k0 = kc * 8;
            uint32_t afr[4][4];
            #pragma unroll
            for (int i = 0; i < 4; i++) {
                const float* ra = Ab + (wm + i * 16 + g) * ASTRIDE + k0;
                const float* rb = ra + 8 * ASTRIDE;
                afr[i][0] = f2tf(ra[tg]);
                afr[i][1] = f2tf(rb[tg]);
                afr[i][2] = f2tf(ra[tg + 4]);
                afr[i][3] = f2tf(rb[tg + 4]);
            }
            uint32_t bfr[8][2];
            #pragma unroll
            for (int j = 0; j < 8; j++) {
                int n = wnn + j * 8 + g;
                bfr[j][0] = f2tf(Bb[(k0 + tg) * BSTRIDE + n]);
                bfr[j][1] = f2tf(Bb[(k0 + tg + 4) * BSTRIDE + n]);
            }
            #pragma unroll
            for (int i = 0; i < 4; i++)
                #pragma unroll
                for (int j = 0; j < 8; j++)
                    MMA_TF32(acc[i][j], afr[i], bfr[j][0], bfr[j][1]);
        }
        __syncthreads();
    }
#undef GEMM_PREFETCH

    #pragma unroll
    for (int j = 0; j < 8; j++) {
        const int col = blockIdx.x * BN + wnn + j * 8 + 2 * tg;
        const float2 bb = *(const float2*)(bias + col);
        #pragma unroll
        for (int i = 0; i < 4; i++) {
            const size_t row0 = (size_t)blockIdx.y * BM + wm + i * 16 + g;
            float2 v0, v1;
            v0.x = acc[i][j][0] + bb.x;
            v0.y = acc[i][j][1] + bb.y;
            v1.x = acc[i][j][2] + bb.x;
            v1.y = acc[i][j][3] + bb.y;
            *(float2*)(C + row0 * ldc + col)       = v0;
            *(float2*)(C + (row0 + 8) * ldc + col) = v1;
        }
    }
}

// ---------------------------------------------------------------------------
// Expert GEMM, bf16 m16n8k16, BOTH operands bf16-in-smem with direct packed
// fragment loads (A: bf16 rows; B: K-pair-packed bf16 weights, stride 136 ->
// fragment addr = 8*tg+g mod 32, conflict-free).  64 LDS per tile, zero
// mainloop cvt/pack.  C[z] = A_bf16[z] @ Bp[z] + bias[z] (opt GELU/bf16 out).
// 128x128x32 tile, 128 threads (4 warps 2x2), warp tile 64x64, 3-stage.
// ---------------------------------------------------------------------------
#define XAW 20                               // A row stride in words
#define XABYTES (128 * XAW * 4)              // 10240 B per A stage
#define XB2STR 136                           // packed-B row stride in words
#define XB2ROWS 16                           // BKt/2 pair-rows per tile
#define XB2BYTES (XB2ROWS * XB2STR * 4)      // 8704 B per B stage
#define XSMEM_BYTES (3 * (XABYTES + XB2BYTES))  // 56832

template <bool GELU, bool OUTBF>
__global__ __launch_bounds__(128) void gemm_bf16_kernel(
    const uint16_t* __restrict__ A, int lda, size_t aZ,
    const uint32_t* __restrict__ Bp, int ldbp, size_t bZ,
    const float* __restrict__ bias, int biasZ,
    void* __restrict__ C, int ldc, size_t cZ,
    int Kd, const int* __restrict__ mcount)
{
    const int z = blockIdx.z;
    if (mcount && (int)(blockIdx.y * BM) >= mcount[z]) return;

    extern __shared__ uint8_t xs[];
    const uint32_t abase = (uint32_t)__cvta_generic_to_shared(xs);
    const uint32_t bbase = abase + 3 * XABYTES;

    const int tid  = threadIdx.x;
    const int wid  = tid >> 5;
    const int lane = tid & 31;
    const int wm   = (wid & 1) * 64;
    const int wnn  = (wid >> 1) * 64;
    const int g    = lane >> 2;
    const int tg   = lane & 3;

    // A staging: one row per thread, 4 x 16B chunks (32 bf16)
    const uint16_t* Ag = A + z * aZ + (size_t)(blockIdx.y * BM + tid) * lda;
    // B staging: 16 pair-rows x 128 words; thread -> row tid>>3, 16-word seg
    const int brow = tid >> 3;            // 0..15
    const int bcol = (tid & 7) * 16;      // 0..112
    const uint32_t* Bg = Bp + z * bZ + (size_t)brow * ldbp + blockIdx.x * BN + bcol;
    const uint32_t bsb = bbase + (brow * XB2STR + bcol) * 4;

    const int ntile = Kd / BKt;

#define XPREFETCH(stage, kt)                                                  \
    do {                                                                      \
        const uint16_t* ga = Ag + (kt) * BKt;                                 \
        const uint32_t* gb = Bg + (size_t)(kt) * XB2ROWS * ldbp;              \
        uint32_t sa = abase + (stage) * XABYTES + tid * (XAW * 4);            \
        uint32_t sb = bsb + (stage) * XB2BYTES;                               \
        _Pragma("unroll")                                                     \
        for (int c = 0; c < 4; c++)                                           \
            cp_async16(sa + c * 16, ga + c * 8);                              \
        _Pragma("unroll")                                                     \
        for (int c = 0; c < 4; c++)                                           \
            cp_async16(sb + c * 16, gb + c * 4);                              \
        asm volatile("cp.async.commit_group;");                               \
    } while (0)

    XPREFETCH(0, 0);
    if (ntile > 1) XPREFETCH(1, 1);
    else asm volatile("cp.async.commit_group;");

    float acc[4][8][4];
    #pragma unroll
    for (int i = 0; i < 4; i++)
        #pragma unroll
        for (int j = 0; j < 8; j++) {
            acc[i][j][0] = 0.f; acc[i][j][1] = 0.f;
            acc[i][j][2] = 0.f; acc[i][j][3] = 0.f;
        }

    for (int kt = 0; kt < ntile; kt++) {
        if (kt + 2 < ntile) {
            XPREFETCH((kt + 2) % 3, kt + 2);
            asm volatile("cp.async.wait_group 2;");
        } else if (kt + 1 < ntile) {
            asm volatile("cp.async.wait_group 1;");
        } else {
            asm volatile("cp.async.wait_group 0;");
        }
        __syncthreads();

        const uint32_t* Aw = (const uint32_t*)(xs + (kt % 3) * XABYTES);
        const uint32_t* Bw = (const uint32_t*)(xs + 3 * XABYTES + (kt % 3) * XB2BYTES);

        #pragma unroll
        for (int kc = 0; kc < 2; kc++) {
            const int kw  = kc * 8;     // A word offset
            const int kp0 = kc * 8;     // B pair-row base
            uint32_t afr[4][4];
            #pragma unroll
            for (int i = 0; i < 4; i++) {
                const uint32_t* ra = Aw + (wm + i * 16 + g) * XAW + kw;
                const uint32_t* rb = ra + 8 * XAW;
                afr[i][0] = ra[tg];
                afr[i][1] = rb[tg];
                afr[i][2] = ra[tg + 4];
                afr[i][3] = rb[tg + 4];
            }
            uint32_t bfr[8][2];
            #pragma unroll
            for (int j = 0; j < 8; j++) {
                int n = wnn + j * 8 + g;
                bfr[j][0] = Bw[(kp0 + tg) * XB2STR + n];
                bfr[j][1] = Bw[(kp0 + tg + 4) * XB2STR + n];
            }
            #pragma unroll
            for (int i = 0; i < 4; i++)
                #pragma unroll
                for (int j = 0; j < 8; j++)
                    MMA_BF16(acc[i][j], afr[i], bfr[j][0], bfr[j][1]);
        }
        __syncthreads();
    }
#undef XPREFETCH

    // epilogue
    const float* bz = bias + (size_t)z * biasZ;
    #pragma unroll
    for (int j = 0; j < 8; j++) {
        const int col = blockIdx.x * BN + wnn + j * 8 + 2 * tg;
        const float2 bb = *(const float2*)(bz + col);
        #pragma unroll
        for (int i = 0; i < 4; i++) {
            const size_t row0 = (size_t)blockIdx.y * BM + wm + i * 16 + g;
            float2 v0, v1;
            v0.x = acc[i][j][0] + bb.x;
            v0.y = acc[i][j][1] + bb.y;
            v1.x = acc[i][j][2] + bb.x;
            v1.y = acc[i][j][3] + bb.y;
            if (GELU) {
                v0.x = gelu_fn(v0.x); v0.y = gelu_fn(v0.y);
                v1.x = gelu_fn(v1.x); v1.y = gelu_fn(v1.y);
            }
            if (OUTBF) {
                uint16_t* Cz = (uint16_t*)C + z * cZ;
                *(uint32_t*)(Cz + row0 * ldc + col)       = pack_bf16(v0.x, v0.y);
                *(uint32_t*)(Cz + (row0 + 8) * ldc + col) = pack_bf16(v1.x, v1.y);
            } else {
                float* Cz = (float*)C + z * cZ;
                *(float2*)(Cz + row0 * ldc + col)       = v0;
                *(float2*)(Cz + (row0 + 8) * ldc + col) = v1;
            }
        }
    }
}

// ---------------------------------------------------------------------------
// Flash attention, tf32 tensor cores (R7-exact).
// ---------------------------------------------------------------------------
__global__ __launch_bounds__(128) void attn_mma_kernel(
    const float* __restrict__ Q, const float* __restrict__ Kb,
    const float* __restrict__ V, const int* __restrict__ mask,
    float* __restrict__ O)
{
    __shared__ uint32_t sK[64][68];
    __shared__ uint32_t sV[64][72];
    __shared__ uint32_t sP[4][16][36];
    __shared__ int      sM[64];

    const int tid  = threadIdx.x;
    const int w    = tid >> 5;
    const int lane = tid & 31;
    const int g    = lane >> 2;
    const int tg   = lane & 3;

    const int bh = blockIdx.y;
    const int b  = bh >> 3, h = bh & 7;
    const int q0 = blockIdx.x << 6;
    const size_t rowbase = (size_t)b * Cn;

    const float* QB = Q  + (rowbase + q0) * Dn + h * HDn;
    const float* KB = Kb + rowbase * Dn + h * HDn;
    const float* VB = V  + rowbase * Dn + h * HDn;
    const int*   MB = mask + b * Cn;

    #pragma unroll
    for (int i = 0; i < 8; i++) {
        int slot = tid + i * 128;
        int r = slot >> 4, c4 = (slot & 15) << 2;
        float4 qv = *(const float4*)(QB + (size_t)r * Dn + c4);
        sK[r][c4 + 0] = f2tf(qv.x * 0.125f);
        sK[r][c4 + 1] = f2tf(qv.y * 0.125f);
        sK[r][c4 + 2] = f2tf(qv.z * 0.125f);
        sK[r][c4 + 3] = f2tf(qv.w * 0.125f);
    }
    __syncthreads();

    const int row0 = w * 16 + g;
    uint32_t qa[8][4];
    #pragma unroll
    for (int ks = 0; ks < 8; ks++) {
        qa[ks][0] = sK[row0][8 * ks + tg];
        qa[ks][1] = sK[row0 + 8][8 * ks + tg];
        qa[ks][2] = sK[row0][8 * ks + tg + 4];
        qa[ks][3] = sK[row0 + 8][8 * ks + tg + 4];
    }
    __syncthreads();

    float o[8][4];
    #pragma unroll
    for (int jn = 0; jn < 8; jn++) {
        o[jn][0] = 0.f; o[jn][1] = 0.f; o[jn][2] = 0.f; o[jn][3] = 0.f;
    }
    float mrun0 = -3.0e38f, mrun1 = -3.0e38f;
    float lrun0 = 0.f, lrun1 = 0.f;

    for (int kt = 0; kt < Cn / 64; kt++) {
        const int k0 = kt * 64;
        #pragma unroll
        for (int i = 0; i < 8; i++) {
            int slot = tid + i * 128;
            int r = slot >> 4, c4 = (slot & 15) << 2;
            float4 kv = *(const float4*)(KB + (size_t)(k0 + r) * Dn + c4);
            float4 vv = *(const float4*)(VB + (size_t)(k0 + r) * Dn + c4);
            sK[r][c4 + 0] = f2tf(kv.x); sK[r][c4 + 1] = f2tf(kv.y);
            sK[r][c4 + 2] = f2tf(kv.z); sK[r][c4 + 3] = f2tf(kv.w);
            sV[r][c4 + 0] = f2tf(vv.x); sV[r][c4 + 1] = f2tf(vv.y);
            sV[r][c4 + 2] = f2tf(vv.z); sV[r][c4 + 3] = f2tf(vv.w);
        }
        if (tid < 64) sM[tid] = MB[k0 + tid];
        __syncthreads();

        #pragma unroll
        for (int kc = 0; kc < 2; kc++) {
            float sacc[4][4];
            #pragma unroll
            for (int j = 0; j < 4; j++) {
                sacc[j][0] = 0.f; sacc[j][1] = 0.f;
                sacc[j][2] = 0.f; sacc[j][3] = 0.f;
            }
            #pragma unroll
            for (int ks = 0; ks < 8; ks++) {
                #pragma unroll
                for (int j = 0; j < 4; j++) {
                    int n = kc * 32 + 8 * j + g;
                    uint32_t b0 = sK[n][8 * ks + tg];
                    uint32_t b1 = sK[n][8 * ks + tg + 4];
                    MMA_TF32(sacc[j], qa[ks], b0, b1);
                }
            }

            #pragma unroll
            for (int j = 0; j < 4; j++) {
                int c = kc * 32 + 8 * j + 2 * tg;
                if (sM[c] == 0)     { sacc[j][0] = -1e10f; sacc[j][2] = -1e10f; }
                if (sM[c + 1] == 0) { sacc[j][1] = -1e10f; sacc[j][3] = -1e10f; }
            }

            float mx0 = -3.0e38f, mx1 = -3.0e38f;
            #pragma unroll
            for (int j = 0; j < 4; j++) {
                mx0 = fmaxf(mx0, fmaxf(sacc[j][0], sacc[j][1]));
                mx1 = fmaxf(mx1, fmaxf(sacc[j][2], sacc[j][3]));
            }
            mx0 = fmaxf(mx0, __shfl_xor_sync(0xffffffffu, mx0, 1));
            mx0 = fmaxf(mx0, __shfl_xor_sync(0xffffffffu, mx0, 2));
            mx1 = fmaxf(mx1, __shfl_xor_sync(0xffffffffu, mx1, 1));
            mx1 = fmaxf(mx1, __shfl_xor_sync(0xffffffffu, mx1, 2));

            float mnew0 = fmaxf(mrun0, mx0);
            float mnew1 = fmaxf(mrun1, mx1);
            float corr0 = __expf(mrun0 - mnew0);
            float corr1 = __expf(mrun1 - mnew1);
            mrun0 = mnew0; mrun1 = mnew1;

            float p[4][4];
            float ls0 = 0.f, ls1 = 0.f;
            #pragma unroll
            for (int j = 0; j < 4; j++) {
                p[j][0] = __expf(sacc[j][0] - mnew0);
                p[j][1] = __expf(sacc[j][1] - mnew0);
                p[j][2] = __expf(sacc[j][2] - mnew1);
                p[j][3] = __expf(sacc[j][3] - mnew1);
                ls0 += p[j][0] + p[j][1];
                ls1 += p[j][2] + p[j][3];
            }
            ls0 += __shfl_xor_sync(0xffffffffu, ls0, 1);
            ls0 += __shfl_xor_sync(0xffffffffu, ls0, 2);
            ls1 += __shfl_xor_sync(0xffffffffu, ls1, 1);
            ls1 += __shfl_xor_sync(0xffffffffu, ls1, 2);
            lrun0 = lrun0 * corr0 + ls0;
            lrun1 = lrun1 * corr1 + ls1;

            #pragma unroll
            for (int jn = 0; jn < 8; jn++) {
                o[jn][0] *= corr0; o[jn][1] *= corr0;
                o[jn][2] *= corr1; o[jn][3] *= corr1;
            }

            #pragma unroll
            for (int j = 0; j < 4; j++) {
                int c = 8 * j + 2 * tg;
                sP[w][g][c]         = f2tf(p[j][0]);
                sP[w][g][c + 1]     = f2tf(p[j][1]);
                sP[w][g + 8][c]     = f2tf(p[j][2]);
                sP[w][g + 8][c + 1] = f2tf(p[j][3]);
            }
            __syncwarp();

            uint32_t pa[4][4];
            #pragma unroll
            for (int ks = 0; ks < 4; ks++) {
                pa[ks][0] = sP[w][g][8 * ks + tg];
                pa[ks][1] = sP[w][g + 8][8 * ks + tg];
                pa[ks][2] = sP[w][g][8 * ks + tg + 4];
                pa[ks][3] = sP[w][g + 8][8 * ks + tg + 4];
            }
            __syncwarp();

            #pragma unroll
            for (int ks = 0; ks < 4; ks++) {
                int kr = kc * 32 + 8 * ks;
                #pragma unroll
                for (int jn = 0; jn < 8; jn++) {
                    uint32_t b0 = sV[kr + tg][8 * jn + g];
                    uint32_t b1 = sV[kr + tg + 4][8 * jn + g];
                    MMA_TF32(o[jn], pa[ks], b0, b1);
                }
            }
        }
        __syncthreads();
    }

    const float inv0 = 1.0f / lrun0;
    const float inv1 = 1.0f / lrun1;
    const size_t grow = rowbase + q0 + row0;
    #pragma unroll
    for (int jn = 0; jn < 8; jn++) {
        int col = h * HDn + 8 * jn + 2 * tg;
        float2 v0, v1;
        v0.x = o[jn][0] * inv0; v0.y = o[jn][1] * inv0;
        v1.x = o[jn][2] * inv1; v1.y = o[jn][3] * inv1;
        *(float2*)(O + grow * Dn + col)       = v0;
        *(float2*)(O + (grow + 8) * Dn + col) = v1;
    }
}

// ---------------------------------------------------------------------------
// Residual add + LayerNorm (R7).
// ---------------------------------------------------------------------------
__global__ __launch_bounds__(256) void add_ln_kernel(
    const float* __restrict__ A, const float* __restrict__ R,
    const float* __restrict__ gam, const float* __restrict__ bet,
    float* __restrict__ out)
{
    int w    = (blockIdx.x * 256 + threadIdx.x) >> 5;
    int lane = threadIdx.x & 31;
    const float4* a4 = (const float4*)(A + (size_t)w * Dn);
    const float4* r4 = (const float4*)(R + (size_t)w * Dn);
    float4 v[4];
    float s = 0.0f, s2 = 0.0f;
    #pragma unroll
    for (int i = 0; i < 4; i++) {
        float4 xa = a4[lane + i * 32], xr = r4[lane + i * 32];
        v[i].x = xa.x + xr.x; v[i].y = xa.y + xr.y;
        v[i].z = xa.z + xr.z; v[i].w = xa.w + xr.w;
        s  += v[i].x + v[i].y + v[i].z + v[i].w;
        s2 += v[i].x * v[i].x + v[i].y * v[i].y + v[i].z * v[i].z + v[i].w * v[i].w;
    }
    #pragma unroll
    for (int off = 16; off; off >>= 1) {
        s  += __shfl_xor_sync(0xffffffffu, s,  off);
        s2 += __shfl_xor_sync(0xffffffffu, s2, off);
    }
    float mean = s * (1.0f / Dn);
    float var  = s2 * (1.0f / Dn) - mean * mean;
    float inv  = rsqrtf(var + 1e-5f);
    const float4* g4 = (const float4*)gam;
    const float4* b4 = (const float4*)bet;
    float4* o4 = (float4*)(out + (size_t)w * Dn);
    #pragma unroll
    for (int i = 0; i < 4; i++) {
        float4 g = g4[lane + i * 32], be = b4[lane + i * 32];
        float4 r;
        r.x = (v[i].x - mean) * inv * g.x + be.x;
        r.y = (v[i].y - mean) * inv * g.y + be.y;
        r.z = (v[i].z - mean) * inv * g.z + be.z;
        r.w = (v[i].w - mean) * inv * g.w + be.w;
        o4[lane + i * 32] = r;
    }
}

// ---------------------------------------------------------------------------
// Router (R7).
// ---------------------------------------------------------------------------
__global__ __launch_bounds__(256) void router_kernel(
    const float* __restrict__ src, const float* __restrict__ rw,
    int* __restrict__ topi, float* __restrict__ topw)
{
    int w    = (blockIdx.x * 256 + threadIdx.x) >> 5;
    int lane = threadIdx.x & 31;
    const float* xr = src + (size_t)w * Dn;
    float acc[8] = {0, 0, 0, 0, 0, 0, 0, 0};
    for (int d = lane; d < Dn; d += 32) {
        float xv = xr[d];
        const float4* r4 = (const float4*)(rw + d * 8);
        float4 r0 = r4[0], r1 = r4[1];
        acc[0] += xv * r0.x; acc[1] += xv * r0.y; acc[2] += xv * r0.z; acc[3] += xv * r0.w;
        acc[4] += xv * r1.x; acc[5] += xv * r1.y; acc[6] += xv * r1.z; acc[7] += xv * r1.w;
    }
    #pragma unroll
    for (int e = 0; e < 8; e++)
        #pragma unroll
        for (int off = 16; off; off >>= 1)
            acc[e] += __shfl_xor_sync(0xffffffffu, acc[e], off);

    if (lane == 0) {
        float mx = acc[0];
        #pragma unroll
        for (int e = 1; e < 8; e++) mx = fmaxf(mx, acc[e]);
        float pe[8], sum = 0.0f;
        #pragma unroll
        for (int e = 0; e < 8; e++) { pe[e] = __expf(acc[e] - mx); sum += pe[e]; }
        float isum = 1.0f / sum;
        #pragma unroll
        for (int e = 0; e < 8; e++) pe[e] *= isum;
        int i1 = 0; float v1 = pe[0];
        #pragma unroll
        for (int e = 1; e < 8; e++) if (pe[e] > v1) { v1 = pe[e]; i1 = e; }
        int i2 = -1; float v2 = -1.0f;
        #pragma unroll
        for (int e = 0; e < 8; e++) if (e != i1 && pe[e] > v2) { v2 = pe[e]; i2 = e; }
        float wn = 1.0f / (v1 + v2);
        topi[2 * w]     = i1;  topi[2 * w + 1] = i2;
        topw[2 * w]     = v1 * wn;  topw[2 * w + 1] = v2 * wn;
    }
}

// ---------------------------------------------------------------------------
// Deterministic capacity scan (unchanged).
// ---------------------------------------------------------------------------
__global__ __launch_bounds__(1024) void scan_kernel(
    const int* __restrict__ topi, int* __restrict__ slotpos,
    int* __restrict__ ecnt)
{
    __shared__ int wtot[32][8];
    __shared__ int wbase[32][8];
    int tid = threadIdx.x, lane = tid & 31, wid = tid >> 5;
    int base = tid * 32;

    int eid[32];
    #pragma unroll
    for (int i = 0; i < 32; i++) eid[i] = topi[base + i];

    int c[8];
    #pragma unroll
    for (int e = 0; e < 8; e++) {
        int ce = 0;
        #pragma unroll
        for (int i = 0; i < 32; i++) ce += (eid[i] == e);
        c[e] = ce;
    }

    int inc[8], excl[8];
    #pragma unroll
    for (int e = 0; e < 8; e++) {
        int v = c[e];
        for (int off = 1; off < 32; off <<= 1) {
            int n = __shfl_up_sync(0xffffffffu, v, off);
            if (lane >= off) v += n;
        }
        inc[e] = v; excl[e] = v - c[e];
    }
    if (lane == 31) {
        #pragma unroll
        for (int e = 0; e < 8; e++) wtot[wid][e] = inc[e];
    }
    __syncthreads();
    if (wid == 0) {
        #pragma unroll
        for (int e = 0; e < 8; e++) {
            int t = wtot[lane][e];
            int v = t;
            for (int off = 1; off < 32; off <<= 1) {
                int n = __shfl_up_sync(0xffffffffu, v, off);
                if (lane >= off) v += n;
            }
            wbase[lane][e] = v - t;
            if (lane == 31) ecnt[e] = min(v, CAPn);
        }
    }
    __syncthreads();

    int run[8];
    #pragma unroll
    for (int e = 0; e < 8; e++) run[e] = wbase[wid][e] + excl[e];

    #pragma unroll
    for (int i = 0; i < 32; i++) {
        int e = eid[i];
        int p = 0;
        #pragma unroll
        for (int ee = 0; ee < 8; ee++)
            if (e == ee) { p = run[ee]; run[ee] = p + 1; }
        slotpos[base + i] = (p < CAPn) ? p : -1;
    }
}

// ---------------------------------------------------------------------------
// Scatter kept slots into disp[E, CAP, D] as bf16.
// ---------------------------------------------------------------------------
__global__ __launch_bounds__(64) void scatter_kernel(
    const float* __restrict__ src, const int* __restrict__ topi,
    const int* __restrict__ slotpos, uint16_t* __restrict__ disp)
{
    int s = blockIdx.x;
    int p = slotpos[s];
    if (p < 0) return;
    int e   = topi[s];
    int tok = s >> 1;
    const float4* in4 = (const float4*)(src + (size_t)tok * Dn);
    uint2* out = (uint2*)(disp + ((size_t)e * CAPn + p) * Dn);
    int t = threadIdx.x;
    #pragma unroll
    for (int half = 0; half < 2; half++) {
        float4 v = in4[t + half * 64];
        uint2 u;
        u.x = pack_bf16(v.x, v.y);
        u.y = pack_bf16(v.z, v.w);
        out[t + half * 64] = u;
    }
}

// ---------------------------------------------------------------------------
// Combine + LN2 (unchanged).
// ---------------------------------------------------------------------------
__global__ __launch_bounds__(256) void combine_ln_kernel(
    const float* __restrict__ src, const float* __restrict__ y,
    const int* __restrict__ topi, const float* __restrict__ topw,
    const int* __restrict__ slotpos,
    const float* __restrict__ gam, const float* __restrict__ bet,
    float* __restrict__ out)
{
    int w    = (blockIdx.x * 256 + threadIdx.x) >> 5;
    int lane = threadIdx.x & 31;
    const float4* s4 = (const float4*)(src + (size_t)w * Dn);
    float4 v[4];
    #pragma unroll
    for (int i = 0; i < 4; i++) v[i] = s4[lane + i * 32];

    #pragma unroll
    for (int kk = 0; kk < 2; kk++) {
        int slot = 2 * w + kk;
        int p = slotpos[slot];
        if (p >= 0) {
            int e = topi[slot];
            float ww = topw[slot];
            const float4* y4 = (const float4*)(y + ((size_t)e * CAPn + p) * Dn);
            #pragma unroll
            for (int i = 0; i < 4; i++) {
                float4 yy = y4[lane + i * 32];
                v[i].x += ww * yy.x; v[i].y += ww * yy.y;
                v[i].z += ww * yy.z; v[i].w += ww * yy.w;
            }
        }
    }

    float s = 0.0f, s2 = 0.0f;
    #pragma unroll
    for (int i = 0; i < 4; i++) {
        s  += v[i].x + v[i].y + v[i].z + v[i].w;
        s2 += v[i].x * v[i].x + v[i].y * v[i].y + v[i].z * v[i].z + v[i].w * v[i].w;
    }
    #pragma unroll
    for (int off = 16; off; off >>= 1) {
        s  += __shfl_xor_sync(0xffffffffu, s,  off);
        s2 += __shfl_xor_sync(0xffffffffu, s2, off);
    }
    float mean = s * (1.0f / Dn);
    float var  = s2 * (1.0f / Dn) - mean * mean;
    float inv  = rsqrtf(var + 1e-5f);
    const float4* g4 = (const float4*)gam;
    const float4* b4 = (const float4*)bet;
    float4* o4 = (float4*)(out + (size_t)w * Dn);
    #pragma unroll
    for (int i = 0; i < 4; i++) {
        float4 g = g4[lane + i * 32], be = b4[lane + i * 32];
        float4 r;
        r.x = (v[i].x - mean) * inv * g.x + be.x;
        r.y = (v[i].y - mean) * inv * g.y + be.y;
        r.z = (v[i].z - mean) * inv * g.z + be.z;
        r.w = (v[i].w - mean) * inv * g.w + be.w;
        o4[lane + i * 32] = r;
    }
}

// ---------------------------------------------------------------------------
// Launch sequence
// ---------------------------------------------------------------------------
extern "C" void kernel_launch(void* const* d_in, const int* in_sizes, int n_in,
                              void* d_out, int out_size)
{
    const float* x    = (const float*)d_in[0];
    const int*   msk  = (const int*)  d_in[1];
    const float* wq   = (const float*)d_in[2];
    const float* bq   = (const float*)d_in[3];
    const float* wk   = (const float*)d_in[4];
    const float* bk   = (const float*)d_in[5];
    const float* wv   = (const float*)d_in[6];
    const float* bv   = (const float*)d_in[7];
    const float* wo   = (const float*)d_in[8];
    const float* bo   = (const float*)d_in[9];
    const float* ln1g = (const float*)d_in[10];
    const float* ln1b = (const float*)d_in[11];
    const float* ln2g = (const float*)d_in[12];
    const float* ln2b = (const float*)d_in[13];
    const float* rw   = (const float*)d_in[14];
    const float* w1   = (const float*)d_in[15];
    const float* b1   = (const float*)d_in[16];
    const float* w2   = (const float*)d_in[17];
    const float* b2   = (const float*)d_in[18];
    float* out = (float*)d_out;

    float* S = nullptr;
    int*   I = nullptr;
    cudaGetSymbolAddress((void**)&S, g_scratch);
    cudaGetSymbolAddress((void**)&I, g_iscratch);

    float* Qb   = S + OFF_Q;
    float* Kbuf = S + OFF_K;
    float* Vb   = S + OFF_V;
    float* ATT  = S + OFF_ATTN;
    float* PRJ  = S + OFF_PRJ;
    float* SRC  = S + OFF_SRC;
    uint16_t* DISP = (uint16_t*)(S + OFF_DISP);   // bf16 view
    uint16_t* Hb   = (uint16_t*)(S + OFF_H);      // bf16 view
    float* Yb   = S + OFF_Y;
    float* TW   = S + OFF_TOPW;
    uint32_t* W1P = (uint32_t*)(S + OFF_W1P);     // packed bf16 weights
    uint32_t* W2P = (uint32_t*)(S + OFF_W2P);
    int* topi    = I;
    int* slotpos = I + NSLOT;
    int* ecnt    = I + 2 * NSLOT;

    cudaFuncSetAttribute(gemm_tf32_kernel,
                         cudaFuncAttributeMaxDynamicSharedMemorySize, GEMM_SMEM_BYTES);
    cudaFuncSetAttribute(gemm_bf16_kernel<true, true>,
                         cudaFuncAttributeMaxDynamicSharedMemorySize, XSMEM_BYTES);
    cudaFuncSetAttribute(gemm_bf16_kernel<false, false>,
                         cudaFuncAttributeMaxDynamicSharedMemorySize, XSMEM_BYTES);

    dim3 blk(128);
    dim3 gproj(Dn / BN, Tn / BM);

    // pre-pack expert weights to K-pair-packed bf16 (rn -- identical rounding
    // to fragment-time pack; off the critical path, runs first)
    pack_w_kernel<<<2048, 256>>>(w1, W1P, FFn, NWEXP / 2);
    pack_w_kernel<<<2048, 256>>>(w2, W2P, Dn,  NWEXP / 2);

    // --- attention block (R7-exact) ---
    gemm_tf32_kernel<<<gproj, blk, GEMM_SMEM_BYTES>>>(x, Dn, wq, Dn, bq, Qb, Dn, Dn);
    gemm_tf32_kernel<<<gproj, blk, GEMM_SMEM_BYTES>>>(x, Dn, wk, Dn, bk, Kbuf, Dn, Dn);
    gemm_tf32_kernel<<<gproj, blk, GEMM_SMEM_BYTES>>>(x, Dn, wv, Dn, bv, Vb, Dn, Dn);
    attn_mma_kernel<<<dim3(Cn / 64, Bn * Hn), 128>>>(Qb, Kbuf, Vb, msk, ATT);
    gemm_tf32_kernel<<<gproj, blk, GEMM_SMEM_BYTES>>>(ATT, Dn, wo, Dn, bo, PRJ, Dn, Dn);
    add_ln_kernel<<<Tn / 8, 256>>>(x, PRJ, ln1g, ln1b, SRC);

    // --- MoE block ---
    router_kernel<<<Tn / 8, 256>>>(SRC, rw, topi, TW);
    scan_kernel<<<1, 1024>>>(topi, slotpos, ecnt);
    scatter_kernel<<<NSLOT, 64>>>(SRC, topi, slotpos, DISP);

    // batched expert FFN (bf16 both operands): z = expert index
    gemm_bf16_kernel<true, true><<<dim3(FFn / BN, CAPn / BM, En), blk, XSMEM_BYTES>>>(
        DISP, Dn, (size_t)CAPn * Dn,
        W1P,  FFn, (size_t)(Dn / 2) * FFn,
        b1,   FFn,
        Hb,   FFn, (size_t)CAPn * FFn,
        Dn, ecnt);
    gemm_bf16_kernel<false, false><<<dim3(Dn / BN, CAPn / BM, En), blk, XSMEM_BYTES>>>(
        Hb,  FFn, (size_t)CAPn * FFn,
        W2P, Dn,  (size_t)(FFn / 2) * Dn,
        b2,  Dn,
        Yb,  Dn,  (size_t)CAPn * Dn,
        FFn, ecnt);

    combine_ln_kernel<<<Tn / 8, 256>>>(SRC, Yb, topi, TW, slotpos,
                                       ln2g, ln2b, out);
}